// round 1
// baseline (speedup 1.0000x reference)
#include <cuda_runtime.h>
#include <cuda_bf16.h>
#include <cstdint>

// Problem constants
// B=2, R=64, L=512, H=1024, NH=8, HD=64, AH=512
#define LB 2
#define LR 64
#define LL 512
#define LH 1024
#define LNH 8
#define LHD 64
#define LAH 512

// Scratch (device globals: allocation-free rule)
__device__ float g_q[(size_t)LB * LL * LAH];                 // (b, l, c)  c = n*64+d
__device__ float g_k[(size_t)LB * LL * LAH];                 // (b, l, c)
__device__ float g_probs[(size_t)LB * LNH * LL * LL];        // (b, n, q, k)
__device__ float g_v[(size_t)LB * LR * LL * LAH];            // (b, r, l, c) row-major 65536 x 512

// ---------------------------------------------------------------------------
// NT SGEMM: C[m,n] = sum_k A[m,k]*B[n,k] + bias[n]   (A: MxK rm, B: NxK rm)
// 128x128 tile, BK=8, 8x8 micro-tile, 256 threads.
// ROPE epilogue (for Q/K): m == l (M=512 per batch slice), pairs along n.
// ---------------------------------------------------------------------------
template<bool ROPE>
__global__ __launch_bounds__(256)
void sgemm_nt128(const float* __restrict__ A, const float* __restrict__ B,
                 const float* __restrict__ bias, float* __restrict__ C,
                 int M, int N, int K, long sAz, long sCz,
                 const float* __restrict__ sp)
{
    __shared__ float As[8][128];
    __shared__ float Bs[8][128];

    const float* Ab = A + (long)blockIdx.z * sAz;
    float*       Cb = C + (long)blockIdx.z * sCz;

    const int m0 = blockIdx.y * 128;
    const int n0 = blockIdx.x * 128;
    const int tid = threadIdx.x;
    const int tm = tid >> 4;        // 0..15 -> rows tm*8
    const int tn = tid & 15;        // 0..15 -> cols tn*8
    const int lrow = tid >> 1;      // 0..127
    const int lcol = (tid & 1) * 4; // 0 or 4

    float acc[8][8] = {};

    for (int k0 = 0; k0 < K; k0 += 8) {
        float4 av = *(const float4*)(Ab + (long)(m0 + lrow) * K + k0 + lcol);
        float4 bv = *(const float4*)(B  + (long)(n0 + lrow) * K + k0 + lcol);
        As[lcol + 0][lrow] = av.x; As[lcol + 1][lrow] = av.y;
        As[lcol + 2][lrow] = av.z; As[lcol + 3][lrow] = av.w;
        Bs[lcol + 0][lrow] = bv.x; Bs[lcol + 1][lrow] = bv.y;
        Bs[lcol + 2][lrow] = bv.z; Bs[lcol + 3][lrow] = bv.w;
        __syncthreads();
        #pragma unroll
        for (int kk = 0; kk < 8; kk++) {
            float a[8], bb[8];
            #pragma unroll
            for (int i = 0; i < 8; i++) a[i] = As[kk][tm * 8 + i];
            #pragma unroll
            for (int j = 0; j < 8; j++) bb[j] = Bs[kk][tn * 8 + j];
            #pragma unroll
            for (int i = 0; i < 8; i++)
                #pragma unroll
                for (int j = 0; j < 8; j++)
                    acc[i][j] = fmaf(a[i], bb[j], acc[i][j]);
        }
        __syncthreads();
    }

    #pragma unroll
    for (int i = 0; i < 8; i++) {
        const int m = m0 + tm * 8 + i;
        #pragma unroll
        for (int j = 0; j < 8; j++) acc[i][j] += bias[n0 + tn * 8 + j];
        if (ROPE) {
            // q' [2i]   = v0*cos - v1*sin ; q'[2i+1] = v1*cos + v0*sin
            #pragma unroll
            for (int j = 0; j < 8; j += 2) {
                const int c  = n0 + tn * 8 + j;
                const int ii = (c & 63) >> 1;
                const float sn = sp[m * 64 + ii];
                const float cs = sp[m * 64 + 32 + ii];
                const float v0 = acc[i][j], v1 = acc[i][j + 1];
                acc[i][j]     = v0 * cs - v1 * sn;
                acc[i][j + 1] = v1 * cs + v0 * sn;
            }
        }
        #pragma unroll
        for (int j = 0; j < 8; j += 4) {
            float4 o = make_float4(acc[i][j], acc[i][j + 1], acc[i][j + 2], acc[i][j + 3]);
            *(float4*)(Cb + (long)m * N + n0 + tn * 8 + j) = o;
        }
    }
}

// ---------------------------------------------------------------------------
// scores + softmax: one block per (b, n, q) row of 512 scores.
// score = dot64(q_row, k_row) / 8 ; softmax over k.
// ---------------------------------------------------------------------------
__global__ __launch_bounds__(256)
void scores_softmax_kernel(const float* __restrict__ q,
                           const float* __restrict__ k,
                           float* __restrict__ probs)
{
    const int qi = blockIdx.x;   // 0..511
    const int n  = blockIdx.y;   // 0..7
    const int b  = blockIdx.z;   // 0..1

    __shared__ float sq[64];
    __shared__ float redm[8];
    __shared__ float reds[8];

    const int t = threadIdx.x;   // 256
    if (t < 64) sq[t] = q[((size_t)(b * 512 + qi)) * 512 + n * 64 + t];
    __syncthreads();

    float sv[2];
    #pragma unroll
    for (int u = 0; u < 2; u++) {
        const int kk = t + u * 256;
        const float* krow = k + ((size_t)(b * 512 + kk)) * 512 + n * 64;
        float s = 0.f;
        #pragma unroll
        for (int d = 0; d < 64; d += 4) {
            float4 kv = *(const float4*)(krow + d);
            s = fmaf(sq[d], kv.x, s);
            s = fmaf(sq[d + 1], kv.y, s);
            s = fmaf(sq[d + 2], kv.z, s);
            s = fmaf(sq[d + 3], kv.w, s);
        }
        sv[u] = s * 0.125f;
    }

    // block max
    float m = fmaxf(sv[0], sv[1]);
    #pragma unroll
    for (int off = 16; off; off >>= 1) m = fmaxf(m, __shfl_xor_sync(0xffffffffu, m, off));
    if ((t & 31) == 0) redm[t >> 5] = m;
    __syncthreads();
    m = redm[0];
    #pragma unroll
    for (int w = 1; w < 8; w++) m = fmaxf(m, redm[w]);

    // exp + block sum
    const float e0 = expf(sv[0] - m);
    const float e1 = expf(sv[1] - m);
    float s = e0 + e1;
    #pragma unroll
    for (int off = 16; off; off >>= 1) s += __shfl_xor_sync(0xffffffffu, s, off);
    if ((t & 31) == 0) reds[t >> 5] = s;
    __syncthreads();
    s = 0.f;
    #pragma unroll
    for (int w = 0; w < 8; w++) s += reds[w];
    const float inv = 1.f / s;

    float* prow = g_probs + ((size_t)((b * 8 + n) * 512 + qi)) * 512;
    (void)probs;
    prow[t]       = e0 * inv;
    prow[t + 256] = e1 * inv;
}

// ---------------------------------------------------------------------------
// ctx batched NN GEMM: per (b, r, n):
//   C[q, j] = sum_k P[b,n][q,k] * V[b,r][k, n*64+j]       (M=512, N=64, K=512)
// BM=128, BN=64, BK=16, micro 8x4, 256 threads. grid (4, 1, 1024)
// ---------------------------------------------------------------------------
__global__ __launch_bounds__(256)
void sgemm_nn_ctx(const float* __restrict__ P, const float* __restrict__ V,
                  float* __restrict__ C)
{
    __shared__ float As[16][128];
    __shared__ float Bs[16][64];

    const int z  = blockIdx.z;
    const int n  = z & 7;
    const int br = z >> 3;         // b*64 + r
    const int b  = br >> 6;

    const float* A  = P + ((size_t)(b * 8 + n)) * (512 * 512);
    const float* Bv = V + (size_t)br * (512 * 512) + n * 64;
    float*       Cc = C + (size_t)br * (512 * 512) + n * 64;

    const int m0  = blockIdx.x * 128;
    const int tid = threadIdx.x;
    const int tm = tid >> 4;            // rows tm*8
    const int tn = tid & 15;            // cols tn*4
    const int arow = tid >> 2;          // 0..63
    const int acol = (tid & 3) * 4;     // 0,4,8,12
    const int brow = tid >> 4;          // 0..15
    const int bcol = (tid & 15) * 4;    // 0..60

    float acc[8][4] = {};

    for (int k0 = 0; k0 < 512; k0 += 16) {
        #pragma unroll
        for (int h = 0; h < 2; h++) {
            const int r = arow + h * 64;
            float4 av = *(const float4*)(A + (size_t)(m0 + r) * 512 + k0 + acol);
            As[acol + 0][r] = av.x; As[acol + 1][r] = av.y;
            As[acol + 2][r] = av.z; As[acol + 3][r] = av.w;
        }
        float4 bv = *(const float4*)(Bv + (size_t)(k0 + brow) * 512 + bcol);
        *(float4*)&Bs[brow][bcol] = bv;
        __syncthreads();
        #pragma unroll
        for (int kk = 0; kk < 16; kk++) {
            float a[8], bb[4];
            #pragma unroll
            for (int i = 0; i < 8; i++) a[i] = As[kk][tm * 8 + i];
            #pragma unroll
            for (int j = 0; j < 4; j++) bb[j] = Bs[kk][tn * 4 + j];
            #pragma unroll
            for (int i = 0; i < 8; i++)
                #pragma unroll
                for (int j = 0; j < 4; j++)
                    acc[i][j] = fmaf(a[i], bb[j], acc[i][j]);
        }
        __syncthreads();
    }

    #pragma unroll
    for (int i = 0; i < 8; i++) {
        const int m = m0 + tm * 8 + i;
        float4 o = make_float4(acc[i][0], acc[i][1], acc[i][2], acc[i][3]);
        *(float4*)(Cc + (size_t)m * 512 + tn * 4) = o;
    }
}

// ---------------------------------------------------------------------------
extern "C" void kernel_launch(void* const* d_in, const int* in_sizes, int n_in,
                              void* d_out, int out_size)
{
    const float* hidden = (const float*)d_in[0];   // (2,64,512,1024)
    const float* sp     = (const float*)d_in[1];   // (512,64)
    const float* Wq     = (const float*)d_in[2];   // (512,1024)
    const float* bq     = (const float*)d_in[3];
    const float* Wk     = (const float*)d_in[4];
    const float* bk     = (const float*)d_in[5];
    const float* Wv     = (const float*)d_in[6];
    const float* bv     = (const float*)d_in[7];
    float* out = (float*)d_out;
    (void)in_sizes; (void)n_in; (void)out_size;

    float *qp, *kp, *pp, *vp;
    cudaGetSymbolAddress((void**)&qp, g_q);
    cudaGetSymbolAddress((void**)&kp, g_k);
    cudaGetSymbolAddress((void**)&pp, g_probs);
    cudaGetSymbolAddress((void**)&vp, g_v);

    dim3 blk(256);

    // Q/K projection + RoPE: per batch, M=512 rows of hidden[b,0,:,:]
    const long sA = (long)LR * LL * LH;   // batch stride into hidden (r=0 slice)
    const long sC = (long)LL * LAH;
    sgemm_nt128<true><<<dim3(4, 4, 2), blk>>>(hidden, Wq, bq, qp, 512, 512, 1024, sA, sC, sp);
    sgemm_nt128<true><<<dim3(4, 4, 2), blk>>>(hidden, Wk, bk, kp, 512, 512, 1024, sA, sC, sp);

    // scores + softmax -> g_probs
    scores_softmax_kernel<<<dim3(512, 8, 2), blk>>>(qp, kp, pp);

    // V projection: M = B*R*L = 65536 rows
    sgemm_nt128<false><<<dim3(4, 512, 1), blk>>>(hidden, Wv, bv, vp, 65536, 512, 1024, 0, 0, nullptr);

    // ctx: batched (b,r,n) NN GEMMs -> output (b,r,q, n*64+d)
    sgemm_nn_ctx<<<dim3(4, 1, 1024), blk>>>(pp, vp, out);
}

// round 2
// speedup vs baseline: 1.5395x; 1.5395x over previous
#include <cuda_runtime.h>
#include <cuda_bf16.h>
#include <cstdint>

#define LB 2
#define LR 64
#define LL 512
#define LH 1024
#define LNH 8
#define LHD 64
#define LAH 512

__device__ float g_q[(size_t)LB * LL * LAH];
__device__ float g_k[(size_t)LB * LL * LAH];
__device__ float g_probs[(size_t)LB * LNH * LL * LL];
__device__ float g_v[(size_t)LB * LR * LL * LAH];

__device__ __forceinline__ uint32_t f2tf32(float f) {
    uint32_t r;
    asm("cvt.rna.tf32.f32 %0, %1;" : "=r"(r) : "f"(f));
    return r;
}

__device__ __forceinline__ void mma_tf32(float c[4], const uint32_t a[4], const uint32_t b[2]) {
    asm volatile(
        "mma.sync.aligned.m16n8k8.row.col.f32.tf32.tf32.f32 "
        "{%0,%1,%2,%3}, {%4,%5,%6,%7}, {%8,%9}, {%0,%1,%2,%3};"
        : "+f"(c[0]), "+f"(c[1]), "+f"(c[2]), "+f"(c[3])
        : "r"(a[0]), "r"(a[1]), "r"(a[2]), "r"(a[3]), "r"(b[0]), "r"(b[1]));
}

// ---------------------------------------------------------------------------
// fp32 NT SGEMM w/ RoPE epilogue — used only for the small Q/K projections.
// ---------------------------------------------------------------------------
__global__ __launch_bounds__(256)
void sgemm_nt128_rope(const float* __restrict__ A, const float* __restrict__ B,
                      const float* __restrict__ bias, float* __restrict__ C,
                      int M, int N, int K, long sAz, long sCz,
                      const float* __restrict__ sp)
{
    __shared__ float As[8][128];
    __shared__ float Bs[8][128];

    const float* Ab = A + (long)blockIdx.z * sAz;
    float*       Cb = C + (long)blockIdx.z * sCz;

    const int m0 = blockIdx.y * 128;
    const int n0 = blockIdx.x * 128;
    const int tid = threadIdx.x;
    const int tm = tid >> 4;
    const int tn = tid & 15;
    const int lrow = tid >> 1;
    const int lcol = (tid & 1) * 4;

    float acc[8][8] = {};

    for (int k0 = 0; k0 < K; k0 += 8) {
        float4 av = *(const float4*)(Ab + (long)(m0 + lrow) * K + k0 + lcol);
        float4 bv = *(const float4*)(B  + (long)(n0 + lrow) * K + k0 + lcol);
        As[lcol + 0][lrow] = av.x; As[lcol + 1][lrow] = av.y;
        As[lcol + 2][lrow] = av.z; As[lcol + 3][lrow] = av.w;
        Bs[lcol + 0][lrow] = bv.x; Bs[lcol + 1][lrow] = bv.y;
        Bs[lcol + 2][lrow] = bv.z; Bs[lcol + 3][lrow] = bv.w;
        __syncthreads();
        #pragma unroll
        for (int kk = 0; kk < 8; kk++) {
            float a[8], bb[8];
            #pragma unroll
            for (int i = 0; i < 8; i++) a[i] = As[kk][tm * 8 + i];
            #pragma unroll
            for (int j = 0; j < 8; j++) bb[j] = Bs[kk][tn * 8 + j];
            #pragma unroll
            for (int i = 0; i < 8; i++)
                #pragma unroll
                for (int j = 0; j < 8; j++)
                    acc[i][j] = fmaf(a[i], bb[j], acc[i][j]);
        }
        __syncthreads();
    }

    #pragma unroll
    for (int i = 0; i < 8; i++) {
        const int m = m0 + tm * 8 + i;
        #pragma unroll
        for (int j = 0; j < 8; j++) acc[i][j] += bias[n0 + tn * 8 + j];
        #pragma unroll
        for (int j = 0; j < 8; j += 2) {
            const int c  = n0 + tn * 8 + j;
            const int ii = (c & 63) >> 1;
            const float sn = sp[m * 64 + ii];
            const float cs = sp[m * 64 + 32 + ii];
            const float v0 = acc[i][j], v1 = acc[i][j + 1];
            acc[i][j]     = v0 * cs - v1 * sn;
            acc[i][j + 1] = v1 * cs + v0 * sn;
        }
        #pragma unroll
        for (int j = 0; j < 8; j += 4) {
            float4 o = make_float4(acc[i][j], acc[i][j + 1], acc[i][j + 2], acc[i][j + 3]);
            *(float4*)(Cb + (long)m * N + n0 + tn * 8 + j) = o;
        }
    }
}

// ---------------------------------------------------------------------------
// tf32 tensor-core NT GEMM: C[m,n] = sum_k A[m,k]*B[n,k] + bias[n]
// BM=128, BN=128, BK=32, 8 warps (2x4), warp tile 64x32, mma m16n8k8.
// ---------------------------------------------------------------------------
__global__ __launch_bounds__(256)
void tf32_nt_gemm(const float* __restrict__ A, const float* __restrict__ B,
                  const float* __restrict__ bias, float* __restrict__ C,
                  int M, int N, int K)
{
    __shared__ float As[32][132];   // [k][m]
    __shared__ float Bs[32][132];   // [k][n]

    const int m0 = blockIdx.y * 128;
    const int n0 = blockIdx.x * 128;
    const int t  = threadIdx.x;

    // staging indices: each thread loads 4 float4 (16 consecutive k) of one row
    const int srow  = t >> 1;
    const int scol0 = (t & 1) * 16;
    const float* Ag = A + (size_t)(m0 + srow) * K + scol0;
    const float* Bg = B + (size_t)(n0 + srow) * K + scol0;

    const int wid  = t >> 5;
    const int wm   = (wid & 1) * 64;
    const int wn   = (wid >> 1) * 32;
    const int lane = t & 31;
    const int grp  = lane >> 2;
    const int tig  = lane & 3;

    float acc[4][4][4];
    #pragma unroll
    for (int i = 0; i < 4; i++)
        #pragma unroll
        for (int j = 0; j < 4; j++)
            #pragma unroll
            for (int r = 0; r < 4; r++) acc[i][j][r] = 0.f;

    float4 ra[4], rb[4];
    #pragma unroll
    for (int v = 0; v < 4; v++) {
        ra[v] = *(const float4*)(Ag + v * 4);
        rb[v] = *(const float4*)(Bg + v * 4);
    }

    const int NK = K / 32;
    for (int it = 0; it < NK; it++) {
        // store staged regs to smem (tf32-rounded)
        #pragma unroll
        for (int v = 0; v < 4; v++) {
            const int kc = scol0 + v * 4;
            As[kc + 0][srow] = __uint_as_float(f2tf32(ra[v].x));
            As[kc + 1][srow] = __uint_as_float(f2tf32(ra[v].y));
            As[kc + 2][srow] = __uint_as_float(f2tf32(ra[v].z));
            As[kc + 3][srow] = __uint_as_float(f2tf32(ra[v].w));
            Bs[kc + 0][srow] = __uint_as_float(f2tf32(rb[v].x));
            Bs[kc + 1][srow] = __uint_as_float(f2tf32(rb[v].y));
            Bs[kc + 2][srow] = __uint_as_float(f2tf32(rb[v].z));
            Bs[kc + 3][srow] = __uint_as_float(f2tf32(rb[v].w));
        }
        __syncthreads();

        if (it + 1 < NK) {
            const int k0 = (it + 1) * 32;
            #pragma unroll
            for (int v = 0; v < 4; v++) {
                ra[v] = *(const float4*)(Ag + k0 + v * 4);
                rb[v] = *(const float4*)(Bg + k0 + v * 4);
            }
        }

        #pragma unroll
        for (int ks = 0; ks < 4; ks++) {
            const int kb = ks * 8;
            uint32_t af[4][4];
            #pragma unroll
            for (int mi = 0; mi < 4; mi++) {
                const int mr = wm + mi * 16 + grp;
                af[mi][0] = __float_as_uint(As[kb + tig][mr]);
                af[mi][1] = __float_as_uint(As[kb + tig][mr + 8]);
                af[mi][2] = __float_as_uint(As[kb + tig + 4][mr]);
                af[mi][3] = __float_as_uint(As[kb + tig + 4][mr + 8]);
            }
            uint32_t bf[4][2];
            #pragma unroll
            for (int ni = 0; ni < 4; ni++) {
                const int nc = wn + ni * 8 + grp;
                bf[ni][0] = __float_as_uint(Bs[kb + tig][nc]);
                bf[ni][1] = __float_as_uint(Bs[kb + tig + 4][nc]);
            }
            #pragma unroll
            for (int mi = 0; mi < 4; mi++)
                #pragma unroll
                for (int ni = 0; ni < 4; ni++)
                    mma_tf32(acc[mi][ni], af[mi], bf[ni]);
        }
        __syncthreads();
    }

    // epilogue: + bias, write fp32
    #pragma unroll
    for (int mi = 0; mi < 4; mi++) {
        const int row = m0 + wm + mi * 16 + grp;
        #pragma unroll
        for (int ni = 0; ni < 4; ni++) {
            const int col = n0 + wn + ni * 8 + tig * 2;
            const float b0 = bias[col], b1 = bias[col + 1];
            float2 o0 = make_float2(acc[mi][ni][0] + b0, acc[mi][ni][1] + b1);
            float2 o1 = make_float2(acc[mi][ni][2] + b0, acc[mi][ni][3] + b1);
            *(float2*)(C + (size_t)row * N + col)       = o0;
            *(float2*)(C + (size_t)(row + 8) * N + col) = o1;
        }
    }
}

// ---------------------------------------------------------------------------
// scores + softmax (fp32, unchanged)
// ---------------------------------------------------------------------------
__global__ __launch_bounds__(256)
void scores_softmax_kernel(const float* __restrict__ q,
                           const float* __restrict__ k)
{
    const int qi = blockIdx.x;
    const int n  = blockIdx.y;
    const int b  = blockIdx.z;

    __shared__ float sq[64];
    __shared__ float redm[8];
    __shared__ float reds[8];

    const int t = threadIdx.x;
    if (t < 64) sq[t] = q[((size_t)(b * 512 + qi)) * 512 + n * 64 + t];
    __syncthreads();

    float sv[2];
    #pragma unroll
    for (int u = 0; u < 2; u++) {
        const int kk = t + u * 256;
        const float* krow = k + ((size_t)(b * 512 + kk)) * 512 + n * 64;
        float s = 0.f;
        #pragma unroll
        for (int d = 0; d < 64; d += 4) {
            float4 kv = *(const float4*)(krow + d);
            s = fmaf(sq[d], kv.x, s);
            s = fmaf(sq[d + 1], kv.y, s);
            s = fmaf(sq[d + 2], kv.z, s);
            s = fmaf(sq[d + 3], kv.w, s);
        }
        sv[u] = s * 0.125f;
    }

    float m = fmaxf(sv[0], sv[1]);
    #pragma unroll
    for (int off = 16; off; off >>= 1) m = fmaxf(m, __shfl_xor_sync(0xffffffffu, m, off));
    if ((t & 31) == 0) redm[t >> 5] = m;
    __syncthreads();
    m = redm[0];
    #pragma unroll
    for (int w = 1; w < 8; w++) m = fmaxf(m, redm[w]);

    const float e0 = expf(sv[0] - m);
    const float e1 = expf(sv[1] - m);
    float s = e0 + e1;
    #pragma unroll
    for (int off = 16; off; off >>= 1) s += __shfl_xor_sync(0xffffffffu, s, off);
    if ((t & 31) == 0) reds[t >> 5] = s;
    __syncthreads();
    s = 0.f;
    #pragma unroll
    for (int w = 0; w < 8; w++) s += reds[w];
    const float inv = 1.f / s;

    float* prow = g_probs + ((size_t)((b * 8 + n) * 512 + qi)) * 512;
    prow[t]       = e0 * inv;
    prow[t + 256] = e1 * inv;
}

// ---------------------------------------------------------------------------
// tf32 tensor-core ctx GEMM (NN): per (b,r,n):
//   C[q,j] = sum_k P[b,n][q,k] * V[b,r][k, n*64+j]    M=512,N=64,K=512
// BM=128, BN=64, BK=32, 8 warps (4x2), warp tile 32x32.
// ---------------------------------------------------------------------------
__global__ __launch_bounds__(256)
void tf32_ctx_gemm(const float* __restrict__ P, const float* __restrict__ V,
                   float* __restrict__ C)
{
    __shared__ float As[32][132];  // [k][m] of P
    __shared__ float Bs[32][68];   // [k][n] of V slice

    const int z  = blockIdx.z;
    const int n  = z & 7;
    const int br = z >> 3;
    const int b  = br >> 6;

    const float* Ag0 = P + ((size_t)(b * 8 + n)) * (512 * 512);
    const float* Bv  = V + (size_t)br * (512 * 512) + n * 64;
    float*       Cc  = C + (size_t)br * (512 * 512) + n * 64;

    const int m0 = blockIdx.x * 128;
    const int t  = threadIdx.x;

    // A staging: row = t>>1 (0..127), 16 consecutive k at (t&1)*16
    const int arow  = t >> 1;
    const int acol0 = (t & 1) * 16;
    const float* Ag = Ag0 + (size_t)(m0 + arow) * 512 + acol0;
    // B staging: 32x64 tile, each thread 2 float4: row=t>>3 (0..31), col=(t&7)*8
    const int brow = t >> 3;
    const int bcol = (t & 7) * 8;

    const int wid  = t >> 5;
    const int wm   = (wid & 3) * 32;
    const int wn   = (wid >> 2) * 32;
    const int lane = t & 31;
    const int grp  = lane >> 2;
    const int tig  = lane & 3;

    float acc[2][4][4];
    #pragma unroll
    for (int i = 0; i < 2; i++)
        #pragma unroll
        for (int j = 0; j < 4; j++)
            #pragma unroll
            for (int r = 0; r < 4; r++) acc[i][j][r] = 0.f;

    float4 ra[4], rb[2];
    #pragma unroll
    for (int v = 0; v < 4; v++) ra[v] = *(const float4*)(Ag + v * 4);
    rb[0] = *(const float4*)(Bv + (size_t)brow * 512 + bcol);
    rb[1] = *(const float4*)(Bv + (size_t)brow * 512 + bcol + 4);

    for (int it = 0; it < 16; it++) {
        #pragma unroll
        for (int v = 0; v < 4; v++) {
            const int kc = acol0 + v * 4;
            As[kc + 0][arow] = __uint_as_float(f2tf32(ra[v].x));
            As[kc + 1][arow] = __uint_as_float(f2tf32(ra[v].y));
            As[kc + 2][arow] = __uint_as_float(f2tf32(ra[v].z));
            As[kc + 3][arow] = __uint_as_float(f2tf32(ra[v].w));
        }
        Bs[brow][bcol + 0] = __uint_as_float(f2tf32(rb[0].x));
        Bs[brow][bcol + 1] = __uint_as_float(f2tf32(rb[0].y));
        Bs[brow][bcol + 2] = __uint_as_float(f2tf32(rb[0].z));
        Bs[brow][bcol + 3] = __uint_as_float(f2tf32(rb[0].w));
        Bs[brow][bcol + 4] = __uint_as_float(f2tf32(rb[1].x));
        Bs[brow][bcol + 5] = __uint_as_float(f2tf32(rb[1].y));
        Bs[brow][bcol + 6] = __uint_as_float(f2tf32(rb[1].z));
        Bs[brow][bcol + 7] = __uint_as_float(f2tf32(rb[1].w));
        __syncthreads();

        if (it + 1 < 16) {
            const int k0 = (it + 1) * 32;
            #pragma unroll
            for (int v = 0; v < 4; v++) ra[v] = *(const float4*)(Ag + k0 + v * 4);
            rb[0] = *(const float4*)(Bv + (size_t)(k0 + brow) * 512 + bcol);
            rb[1] = *(const float4*)(Bv + (size_t)(k0 + brow) * 512 + bcol + 4);
        }

        #pragma unroll
        for (int ks = 0; ks < 4; ks++) {
            const int kb = ks * 8;
            uint32_t af[2][4];
            #pragma unroll
            for (int mi = 0; mi < 2; mi++) {
                const int mr = wm + mi * 16 + grp;
                af[mi][0] = __float_as_uint(As[kb + tig][mr]);
                af[mi][1] = __float_as_uint(As[kb + tig][mr + 8]);
                af[mi][2] = __float_as_uint(As[kb + tig + 4][mr]);
                af[mi][3] = __float_as_uint(As[kb + tig + 4][mr + 8]);
            }
            uint32_t bf[4][2];
            #pragma unroll
            for (int ni = 0; ni < 4; ni++) {
                const int nc = wn + ni * 8 + grp;
                bf[ni][0] = __float_as_uint(Bs[kb + tig][nc]);
                bf[ni][1] = __float_as_uint(Bs[kb + tig + 4][nc]);
            }
            #pragma unroll
            for (int mi = 0; mi < 2; mi++)
                #pragma unroll
                for (int ni = 0; ni < 4; ni++)
                    mma_tf32(acc[mi][ni], af[mi], bf[ni]);
        }
        __syncthreads();
    }

    #pragma unroll
    for (int mi = 0; mi < 2; mi++) {
        const int row = m0 + wm + mi * 16 + grp;
        #pragma unroll
        for (int ni = 0; ni < 4; ni++) {
            const int col = wn + ni * 8 + tig * 2;
            *(float2*)(Cc + (size_t)row * 512 + col)       = make_float2(acc[mi][ni][0], acc[mi][ni][1]);
            *(float2*)(Cc + (size_t)(row + 8) * 512 + col) = make_float2(acc[mi][ni][2], acc[mi][ni][3]);
        }
    }
}

// ---------------------------------------------------------------------------
extern "C" void kernel_launch(void* const* d_in, const int* in_sizes, int n_in,
                              void* d_out, int out_size)
{
    const float* hidden = (const float*)d_in[0];
    const float* sp     = (const float*)d_in[1];
    const float* Wq     = (const float*)d_in[2];
    const float* bq     = (const float*)d_in[3];
    const float* Wk     = (const float*)d_in[4];
    const float* bk     = (const float*)d_in[5];
    const float* Wv     = (const float*)d_in[6];
    const float* bv     = (const float*)d_in[7];
    float* out = (float*)d_out;
    (void)in_sizes; (void)n_in; (void)out_size;

    float *qp, *kp, *pp, *vp;
    cudaGetSymbolAddress((void**)&qp, g_q);
    cudaGetSymbolAddress((void**)&kp, g_k);
    cudaGetSymbolAddress((void**)&pp, g_probs);
    cudaGetSymbolAddress((void**)&vp, g_v);

    dim3 blk(256);

    const long sA = (long)LR * LL * LH;
    const long sC = (long)LL * LAH;
    sgemm_nt128_rope<<<dim3(4, 4, 2), blk>>>(hidden, Wq, bq, qp, 512, 512, 1024, sA, sC, sp);
    sgemm_nt128_rope<<<dim3(4, 4, 2), blk>>>(hidden, Wk, bk, kp, 512, 512, 1024, sA, sC, sp);

    scores_softmax_kernel<<<dim3(512, 8, 2), blk>>>(qp, kp);

    // V projection on tensor cores: M=65536, N=512, K=1024
    tf32_nt_gemm<<<dim3(4, 512, 1), blk>>>(hidden, Wv, bv, vp, 65536, 512, 1024);

    // ctx on tensor cores
    tf32_ctx_gemm<<<dim3(4, 1, 1024), blk>>>(pp, vp, out);
}

// round 3
// speedup vs baseline: 3.3582x; 2.1813x over previous
#include <cuda_runtime.h>
#include <cuda_fp16.h>
#include <cstdint>

#define LB 2
#define LR 64
#define LL 512
#define LH 1024
#define LAH 512

__device__ float  g_q[(size_t)LB * LL * LAH];
__device__ float  g_k[(size_t)LB * LL * LAH];
__device__ __half g_probs[(size_t)LB * 8 * LL * LL];
__device__ __half g_v[(size_t)LB * LR * LL * LAH];

// ---------------------------------------------------------------------------
// helpers
// ---------------------------------------------------------------------------
__device__ __forceinline__ void ldsm4(uint32_t r[4], uint32_t a) {
    asm volatile("ldmatrix.sync.aligned.m8n8.x4.shared.b16 {%0,%1,%2,%3}, [%4];"
                 : "=r"(r[0]), "=r"(r[1]), "=r"(r[2]), "=r"(r[3]) : "r"(a));
}
__device__ __forceinline__ void ldsm4t(uint32_t r[4], uint32_t a) {
    asm volatile("ldmatrix.sync.aligned.m8n8.x4.trans.shared.b16 {%0,%1,%2,%3}, [%4];"
                 : "=r"(r[0]), "=r"(r[1]), "=r"(r[2]), "=r"(r[3]) : "r"(a));
}
__device__ __forceinline__ void mma16816(float c[4], const uint32_t a[4], const uint32_t b[2]) {
    asm volatile(
        "mma.sync.aligned.m16n8k16.row.col.f32.f16.f16.f32 "
        "{%0,%1,%2,%3}, {%4,%5,%6,%7}, {%8,%9}, {%0,%1,%2,%3};"
        : "+f"(c[0]), "+f"(c[1]), "+f"(c[2]), "+f"(c[3])
        : "r"(a[0]), "r"(a[1]), "r"(a[2]), "r"(a[3]), "r"(b[0]), "r"(b[1]));
}
__device__ __forceinline__ uint32_t pk2(float x, float y) {
    __half2 h = __floats2half2_rn(x, y);
    return *(uint32_t*)&h;
}
__device__ __forceinline__ uint4 cvt8(float4 a, float4 b) {
    uint4 u;
    u.x = pk2(a.x, a.y); u.y = pk2(a.z, a.w);
    u.z = pk2(b.x, b.y); u.w = pk2(b.z, b.w);
    return u;
}
// byte offset in a [rows][32-half] tile; 16B chunk swizzle: c ^ ((row>>1)&3)
__device__ __forceinline__ uint32_t swA(int row, int c) {
    return (uint32_t)((row * 4 + (c ^ ((row >> 1) & 3))) * 16);
}
// byte offset in a [rows][64-half] tile; chunk swizzle: c ^ (row&7)
__device__ __forceinline__ uint32_t swB8(int row, int c) {
    return (uint32_t)((row * 8 + (c ^ (row & 7))) * 16);
}

// ---------------------------------------------------------------------------
// fp16 NT GEMM: C[m,n] = sum_k A[m,k]*B[n,k] + bias[n]
// BM=128 BN=128 BK=32, 8 warps (2m x 4n), warp tile 64x32, mma m16n8k16.
// MODE 0: half output (V proj).  MODE 1: fp32 output + RoPE (Q/K proj).
// ---------------------------------------------------------------------------
template<int MODE>
__global__ __launch_bounds__(256)
void h16_nt_gemm(const float* __restrict__ A, const float* __restrict__ B,
                 const float* __restrict__ bias, void* __restrict__ Cv,
                 int M, int N, int K, long sAz, long sCz,
                 const float* __restrict__ sp)
{
    __shared__ __align__(16) unsigned char sm[2 * 16384]; // stage: A 8KB + B 8KB
    const uint32_t smBase = (uint32_t)__cvta_generic_to_shared(sm);

    const int m0 = blockIdx.y * 128;
    const int n0 = blockIdx.x * 128;
    const int t  = threadIdx.x;

    const int srow  = t >> 1;
    const int cbase = (t & 1) * 2;
    const float* Ag = A + (long)blockIdx.z * sAz + (size_t)(m0 + srow) * K + cbase * 8;
    const float* Bg = B + (size_t)(n0 + srow) * K + cbase * 8;

    const int wid  = t >> 5;
    const int wm   = (wid & 1) * 64;
    const int wn   = (wid >> 1) * 32;
    const int lane = t & 31;
    const int grp  = lane >> 2;
    const int tig  = lane & 3;

    // ldmatrix per-lane address components
    const int aRow = wm + (lane & 15);
    const int aCs  = lane >> 4;                       // chunk select 0/1
    const int bRow = wn + (lane & 7) + 8 * (lane >> 4);
    const int bCs  = (lane >> 3) & 1;

    float acc[4][4][4] = {};

    float4 ra[4], rb[4];
    #pragma unroll
    for (int v = 0; v < 4; v++) { ra[v] = *(const float4*)(Ag + v * 4); rb[v] = *(const float4*)(Bg + v * 4); }
    {
        uint32_t oA = smBase, oB = smBase + 8192;
        *(uint4*)(sm + (swA(srow, cbase)     + (oA - smBase))) = cvt8(ra[0], ra[1]);
        *(uint4*)(sm + (swA(srow, cbase + 1) + (oA - smBase))) = cvt8(ra[2], ra[3]);
        *(uint4*)(sm + (swA(srow, cbase)     + (oB - smBase))) = cvt8(rb[0], rb[1]);
        *(uint4*)(sm + (swA(srow, cbase + 1) + (oB - smBase))) = cvt8(rb[2], rb[3]);
    }
    __syncthreads();

    const int NK = K / 32;
    for (int it = 0; it < NK; it++) {
        const int s = it & 1;
        if (it + 1 < NK) {
            const int k0 = (it + 1) * 32;
            #pragma unroll
            for (int v = 0; v < 4; v++) { ra[v] = *(const float4*)(Ag + k0 + v * 4); rb[v] = *(const float4*)(Bg + k0 + v * 4); }
        }
        const uint32_t bA = smBase + s * 16384;
        const uint32_t bB = bA + 8192;
        #pragma unroll
        for (int ks = 0; ks < 2; ks++) {
            uint32_t af[4][4], bf[2][4];
            #pragma unroll
            for (int mi = 0; mi < 4; mi++)
                ldsm4(af[mi], bA + swA(aRow + mi * 16, 2 * ks + aCs));
            #pragma unroll
            for (int nj = 0; nj < 2; nj++)
                ldsm4(bf[nj], bB + swA(bRow + nj * 16, 2 * ks + bCs));
            #pragma unroll
            for (int mi = 0; mi < 4; mi++)
                #pragma unroll
                for (int ni = 0; ni < 4; ni++)
                    mma16816(acc[mi][ni], af[mi], &bf[ni >> 1][(ni & 1) * 2]);
        }
        if (it + 1 < NK) {
            unsigned char* d = sm + (s ^ 1) * 16384;
            *(uint4*)(d + swA(srow, cbase))            = cvt8(ra[0], ra[1]);
            *(uint4*)(d + swA(srow, cbase + 1))        = cvt8(ra[2], ra[3]);
            *(uint4*)(d + 8192 + swA(srow, cbase))     = cvt8(rb[0], rb[1]);
            *(uint4*)(d + 8192 + swA(srow, cbase + 1)) = cvt8(rb[2], rb[3]);
        }
        __syncthreads();
    }

    // epilogue
    #pragma unroll
    for (int mi = 0; mi < 4; mi++) {
        const int row = m0 + wm + mi * 16 + grp;
        #pragma unroll
        for (int ni = 0; ni < 4; ni++) {
            const int col = n0 + wn + ni * 8 + tig * 2;
            const float b0 = bias[col], b1 = bias[col + 1];
            const float c0 = acc[mi][ni][0] + b0, c1 = acc[mi][ni][1] + b1;
            const float c2 = acc[mi][ni][2] + b0, c3 = acc[mi][ni][3] + b1;
            if (MODE == 0) {
                __half* C = (__half*)Cv;
                *(__half2*)(C + (size_t)row * N + col)       = __floats2half2_rn(c0, c1);
                *(__half2*)(C + (size_t)(row + 8) * N + col) = __floats2half2_rn(c2, c3);
            } else {
                float* C = (float*)Cv + (long)blockIdx.z * sCz;
                const int ii = (col & 63) >> 1;
                float sn = sp[row * 64 + ii], cs = sp[row * 64 + 32 + ii];
                *(float2*)(C + (size_t)row * N + col) = make_float2(c0 * cs - c1 * sn, c1 * cs + c0 * sn);
                sn = sp[(row + 8) * 64 + ii]; cs = sp[(row + 8) * 64 + 32 + ii];
                *(float2*)(C + (size_t)(row + 8) * N + col) = make_float2(c2 * cs - c3 * sn, c3 * cs + c2 * sn);
            }
        }
    }
}

// ---------------------------------------------------------------------------
// scores + softmax (fp32 q/k in, half probs out)
// ---------------------------------------------------------------------------
__global__ __launch_bounds__(256)
void scores_softmax_kernel(const float* __restrict__ q,
                           const float* __restrict__ k)
{
    const int qi = blockIdx.x;
    const int n  = blockIdx.y;
    const int b  = blockIdx.z;

    __shared__ float sq[64];
    __shared__ float redm[8];
    __shared__ float reds[8];

    const int t = threadIdx.x;
    if (t < 64) sq[t] = q[((size_t)(b * 512 + qi)) * 512 + n * 64 + t];
    __syncthreads();

    float sv[2];
    #pragma unroll
    for (int u = 0; u < 2; u++) {
        const int kk = t + u * 256;
        const float* krow = k + ((size_t)(b * 512 + kk)) * 512 + n * 64;
        float s = 0.f;
        #pragma unroll
        for (int d = 0; d < 64; d += 4) {
            float4 kv = *(const float4*)(krow + d);
            s = fmaf(sq[d], kv.x, s);
            s = fmaf(sq[d + 1], kv.y, s);
            s = fmaf(sq[d + 2], kv.z, s);
            s = fmaf(sq[d + 3], kv.w, s);
        }
        sv[u] = s * 0.125f;
    }

    float m = fmaxf(sv[0], sv[1]);
    #pragma unroll
    for (int off = 16; off; off >>= 1) m = fmaxf(m, __shfl_xor_sync(0xffffffffu, m, off));
    if ((t & 31) == 0) redm[t >> 5] = m;
    __syncthreads();
    m = redm[0];
    #pragma unroll
    for (int w = 1; w < 8; w++) m = fmaxf(m, redm[w]);

    const float e0 = expf(sv[0] - m);
    const float e1 = expf(sv[1] - m);
    float s = e0 + e1;
    #pragma unroll
    for (int off = 16; off; off >>= 1) s += __shfl_xor_sync(0xffffffffu, s, off);
    if ((t & 31) == 0) reds[t >> 5] = s;
    __syncthreads();
    s = 0.f;
    #pragma unroll
    for (int w = 0; w < 8; w++) s += reds[w];
    const float inv = 1.f / s;

    __half* prow = g_probs + ((size_t)((b * 8 + n) * 512 + qi)) * 512;
    prow[t]       = __float2half_rn(e0 * inv);
    prow[t + 256] = __float2half_rn(e1 * inv);
}

// ---------------------------------------------------------------------------
// fp16 ctx GEMM (NN): per (b,r,n): C[q,j] = sum_k P[q,k] * V[k, n*64+j]
// M=512 N=64 K=512; BM=128 BN=64 BK=32; 8 warps (4m x 2n), warp 32x32.
// A via ldmatrix, B via ldmatrix.trans.
// ---------------------------------------------------------------------------
__global__ __launch_bounds__(256)
void h16_ctx_gemm(const __half* __restrict__ P, const __half* __restrict__ V,
                  float* __restrict__ C)
{
    __shared__ __align__(16) unsigned char sm[2 * 12288]; // A 8KB + B 4KB per stage
    const uint32_t smBase = (uint32_t)__cvta_generic_to_shared(sm);

    const int z  = blockIdx.z;
    const int n  = z & 7;
    const int br = z >> 3;
    const int b  = br >> 6;

    const __half* P0 = P + ((size_t)(b * 8 + n)) * (512 * 512);
    const __half* Vg = V + (size_t)br * (512 * 512) + n * 64;
    float*        Cc = C + (size_t)br * (512 * 512) + n * 64;

    const int m0 = blockIdx.x * 128;
    const int t  = threadIdx.x;

    const int arow  = t >> 1;
    const int acb   = (t & 1) * 2;
    const int bkrow = t >> 3;
    const int bc    = t & 7;

    const int wid  = t >> 5;
    const int wm   = (wid & 3) * 32;
    const int wn   = (wid >> 2) * 32;
    const int lane = t & 31;
    const int grp  = lane >> 2;
    const int tig  = lane & 3;

    const int aRow = wm + (lane & 15);
    const int aCs  = lane >> 4;
    const int bK   = (lane & 7) + 8 * ((lane >> 3) & 1);
    const int bCn  = (wn >> 3) + (lane >> 4);

    float acc[2][4][4] = {};

    uint4 ua0, ua1, ub;
    ua0 = *(const uint4*)(P0 + (size_t)(m0 + arow) * 512 + 8 * acb);
    ua1 = *(const uint4*)(P0 + (size_t)(m0 + arow) * 512 + 8 * (acb + 1));
    ub  = *(const uint4*)(Vg + (size_t)bkrow * 512 + 8 * bc);
    *(uint4*)(sm + swA(arow, acb))     = ua0;
    *(uint4*)(sm + swA(arow, acb + 1)) = ua1;
    *(uint4*)(sm + 8192 + swB8(bkrow, bc)) = ub;
    __syncthreads();

    for (int it = 0; it < 16; it++) {
        const int s = it & 1;
        if (it + 1 < 16) {
            const int k0 = (it + 1) * 32;
            ua0 = *(const uint4*)(P0 + (size_t)(m0 + arow) * 512 + k0 + 8 * acb);
            ua1 = *(const uint4*)(P0 + (size_t)(m0 + arow) * 512 + k0 + 8 * (acb + 1));
            ub  = *(const uint4*)(Vg + (size_t)(k0 + bkrow) * 512 + 8 * bc);
        }
        const uint32_t bA = smBase + s * 12288;
        const uint32_t bB = bA + 8192;
        #pragma unroll
        for (int ks = 0; ks < 2; ks++) {
            uint32_t af[2][4], bf[2][4];
            #pragma unroll
            for (int mi = 0; mi < 2; mi++)
                ldsm4(af[mi], bA + swA(aRow + mi * 16, 2 * ks + aCs));
            #pragma unroll
            for (int nj = 0; nj < 2; nj++)
                ldsm4t(bf[nj], bB + swB8(ks * 16 + bK, bCn + 2 * nj));
            #pragma unroll
            for (int mi = 0; mi < 2; mi++)
                #pragma unroll
                for (int ni = 0; ni < 4; ni++)
                    mma16816(acc[mi][ni], af[mi], &bf[ni >> 1][(ni & 1) * 2]);
        }
        if (it + 1 < 16) {
            unsigned char* d = sm + (s ^ 1) * 12288;
            *(uint4*)(d + swA(arow, acb))     = ua0;
            *(uint4*)(d + swA(arow, acb + 1)) = ua1;
            *(uint4*)(d + 8192 + swB8(bkrow, bc)) = ub;
        }
        __syncthreads();
    }

    #pragma unroll
    for (int mi = 0; mi < 2; mi++) {
        const int row = m0 + wm + mi * 16 + grp;
        #pragma unroll
        for (int ni = 0; ni < 4; ni++) {
            const int col = wn + ni * 8 + tig * 2;
            *(float2*)(Cc + (size_t)row * 512 + col)       = make_float2(acc[mi][ni][0], acc[mi][ni][1]);
            *(float2*)(Cc + (size_t)(row + 8) * 512 + col) = make_float2(acc[mi][ni][2], acc[mi][ni][3]);
        }
    }
}

// ---------------------------------------------------------------------------
extern "C" void kernel_launch(void* const* d_in, const int* in_sizes, int n_in,
                              void* d_out, int out_size)
{
    const float* hidden = (const float*)d_in[0];
    const float* sp     = (const float*)d_in[1];
    const float* Wq     = (const float*)d_in[2];
    const float* bq     = (const float*)d_in[3];
    const float* Wk     = (const float*)d_in[4];
    const float* bk     = (const float*)d_in[5];
    const float* Wv     = (const float*)d_in[6];
    const float* bv     = (const float*)d_in[7];
    float* out = (float*)d_out;
    (void)in_sizes; (void)n_in; (void)out_size;

    float *qp, *kp;
    __half *pp, *vp;
    cudaGetSymbolAddress((void**)&qp, g_q);
    cudaGetSymbolAddress((void**)&kp, g_k);
    cudaGetSymbolAddress((void**)&pp, g_probs);
    cudaGetSymbolAddress((void**)&vp, g_v);

    dim3 blk(256);
    const long sA = (long)LR * LL * LH;   // batch stride (r=0 slice)
    const long sC = (long)LL * LAH;

    // Q/K projections + RoPE (fp16 MMA, fp32 out)
    h16_nt_gemm<1><<<dim3(4, 4, 2), blk>>>(hidden, Wq, bq, qp, 512, 512, 1024, sA, sC, sp);
    h16_nt_gemm<1><<<dim3(4, 4, 2), blk>>>(hidden, Wk, bk, kp, 512, 512, 1024, sA, sC, sp);

    // V projection (fp16 MMA, half out): M=65536
    h16_nt_gemm<0><<<dim3(4, 512, 1), blk>>>(hidden, Wv, bv, vp, 65536, 512, 1024, 0, 0, nullptr);

    // scores + softmax -> half probs
    scores_softmax_kernel<<<dim3(512, 8, 2), blk>>>(qp, kp);

    // ctx (fp16 MMA) -> fp32 out
    h16_ctx_gemm<<<dim3(4, 1, 1024), blk>>>(pp, vp, out);
}

// round 4
// speedup vs baseline: 5.3866x; 1.6040x over previous
#include <cuda_runtime.h>
#include <cuda_fp16.h>
#include <cstdint>

#define LB 2
#define LR 64
#define LL 512
#define LH 1024
#define LAH 512

__device__ __half g_h[(size_t)LB * LR * LL * LH];     // hidden as half
__device__ __half g_wq[LAH * LH], g_wk[LAH * LH], g_wv[LAH * LH];
__device__ __half g_q[(size_t)LB * LL * LAH];         // RoPE'd q (half)
__device__ __half g_k[(size_t)LB * LL * LAH];
__device__ float  g_s[(size_t)LB * 8 * LL * LL];      // raw scores fp32
__device__ __half g_probs[(size_t)LB * 8 * LL * LL];
__device__ __half g_v[(size_t)LB * LR * LL * LAH];

// ---------------------------------------------------------------------------
__device__ __forceinline__ void ldsm4(uint32_t r[4], uint32_t a) {
    asm volatile("ldmatrix.sync.aligned.m8n8.x4.shared.b16 {%0,%1,%2,%3}, [%4];"
                 : "=r"(r[0]), "=r"(r[1]), "=r"(r[2]), "=r"(r[3]) : "r"(a));
}
__device__ __forceinline__ void ldsm4t(uint32_t r[4], uint32_t a) {
    asm volatile("ldmatrix.sync.aligned.m8n8.x4.trans.shared.b16 {%0,%1,%2,%3}, [%4];"
                 : "=r"(r[0]), "=r"(r[1]), "=r"(r[2]), "=r"(r[3]) : "r"(a));
}
__device__ __forceinline__ void mma16816(float c[4], const uint32_t a[4], const uint32_t b[2]) {
    asm volatile(
        "mma.sync.aligned.m16n8k16.row.col.f32.f16.f16.f32 "
        "{%0,%1,%2,%3}, {%4,%5,%6,%7}, {%8,%9}, {%0,%1,%2,%3};"
        : "+f"(c[0]), "+f"(c[1]), "+f"(c[2]), "+f"(c[3])
        : "r"(a[0]), "r"(a[1]), "r"(a[2]), "r"(a[3]), "r"(b[0]), "r"(b[1]));
}
__device__ __forceinline__ uint32_t pk2(float x, float y) {
    __half2 h = __floats2half2_rn(x, y);
    return *(uint32_t*)&h;
}
// [rows][32-half] tile, 16B chunks, swizzle c ^ ((row>>1)&3)
__device__ __forceinline__ uint32_t swA(int row, int c) {
    return (uint32_t)((row * 4 + (c ^ ((row >> 1) & 3))) * 16);
}
// [rows][64-half] tile, 16B chunks, swizzle c ^ (row&7)
__device__ __forceinline__ uint32_t swB8(int row, int c) {
    return (uint32_t)((row * 8 + (c ^ (row & 7))) * 16);
}

// ---------------------------------------------------------------------------
// float -> half conversion (grid-stride, 8 elems/thread/iter)
// ---------------------------------------------------------------------------
__global__ void f2h_kernel(const float* __restrict__ src, __half* __restrict__ dst, long n)
{
    long stride = (long)gridDim.x * blockDim.x * 8;
    for (long j = ((long)blockIdx.x * blockDim.x + threadIdx.x) * 8; j < n; j += stride) {
        float4 a = *(const float4*)(src + j);
        float4 b = *(const float4*)(src + j + 4);
        uint4 u;
        u.x = pk2(a.x, a.y); u.y = pk2(a.z, a.w);
        u.z = pk2(b.x, b.y); u.w = pk2(b.z, b.w);
        *(uint4*)(dst + j) = u;
    }
}

// ---------------------------------------------------------------------------
// Projection GEMM (NT, half in): C[m,n] = sum_k A[m,k]*B[n,k] + bias[n]
// BM=128 BN=128 BK=32, 8 warps (2m x 4n), warp 64x32.
// MODE 0: V proj (half out).  MODE 1: fused Q/K proj + RoPE (half out),
//         blockIdx.z = b*2 + which.
// ---------------------------------------------------------------------------
template<int MODE>
__global__ __launch_bounds__(256)
void h16_proj(const __half* __restrict__ A0,
              const __half* __restrict__ B0, const float* __restrict__ bias0, __half* __restrict__ C0,
              const __half* __restrict__ B1, const float* __restrict__ bias1, __half* __restrict__ C1,
              int N, int K, const float* __restrict__ sp)
{
    __shared__ __align__(16) unsigned char sm[2 * 16384];
    const uint32_t smBase = (uint32_t)__cvta_generic_to_shared(sm);

    const __half* A; const __half* B; const float* bias; __half* C;
    if (MODE == 1) {
        const int b = blockIdx.z >> 1, which = blockIdx.z & 1;
        A = A0 + (size_t)b * ((size_t)LR * LL * LH);
        B = which ? B1 : B0;
        bias = which ? bias1 : bias0;
        C = (which ? C1 : C0) + (size_t)b * LL * LAH;
    } else {
        A = A0; B = B0; bias = bias0; C = C0;
    }

    const int m0 = blockIdx.y * 128;
    const int n0 = blockIdx.x * 128;
    const int t  = threadIdx.x;

    const int srow = t >> 1;
    const int cb   = (t & 1) * 2;
    const __half* Ag = A + (size_t)(m0 + srow) * K + cb * 8;
    const __half* Bg = B + (size_t)(n0 + srow) * K + cb * 8;

    const int wid  = t >> 5;
    const int wm   = (wid & 1) * 64;
    const int wn   = (wid >> 1) * 32;
    const int lane = t & 31;
    const int grp  = lane >> 2;
    const int tig  = lane & 3;

    const int aRow = wm + (lane & 15);
    const int aCs  = lane >> 4;
    const int bRow = wn + (lane & 7) + 8 * (lane >> 4);
    const int bCs  = (lane >> 3) & 1;

    float acc[4][4][4] = {};

    uint4 a0 = *(const uint4*)(Ag), a1 = *(const uint4*)(Ag + 8);
    uint4 b0 = *(const uint4*)(Bg), b1 = *(const uint4*)(Bg + 8);
    *(uint4*)(sm + swA(srow, cb))            = a0;
    *(uint4*)(sm + swA(srow, cb + 1))        = a1;
    *(uint4*)(sm + 8192 + swA(srow, cb))     = b0;
    *(uint4*)(sm + 8192 + swA(srow, cb + 1)) = b1;
    __syncthreads();

    const int NK = K / 32;
    for (int it = 0; it < NK; it++) {
        const int s = it & 1;
        if (it + 1 < NK) {
            const int k0 = (it + 1) * 32;
            a0 = *(const uint4*)(Ag + k0); a1 = *(const uint4*)(Ag + k0 + 8);
            b0 = *(const uint4*)(Bg + k0); b1 = *(const uint4*)(Bg + k0 + 8);
        }
        const uint32_t bA = smBase + s * 16384;
        const uint32_t bB = bA + 8192;
        #pragma unroll
        for (int ks = 0; ks < 2; ks++) {
            uint32_t af[4][4], bf[2][4];
            #pragma unroll
            for (int mi = 0; mi < 4; mi++)
                ldsm4(af[mi], bA + swA(aRow + mi * 16, 2 * ks + aCs));
            #pragma unroll
            for (int nj = 0; nj < 2; nj++)
                ldsm4(bf[nj], bB + swA(bRow + nj * 16, 2 * ks + bCs));
            #pragma unroll
            for (int mi = 0; mi < 4; mi++)
                #pragma unroll
                for (int ni = 0; ni < 4; ni++)
                    mma16816(acc[mi][ni], af[mi], &bf[ni >> 1][(ni & 1) * 2]);
        }
        if (it + 1 < NK) {
            unsigned char* d = sm + (s ^ 1) * 16384;
            *(uint4*)(d + swA(srow, cb))            = a0;
            *(uint4*)(d + swA(srow, cb + 1))        = a1;
            *(uint4*)(d + 8192 + swA(srow, cb))     = b0;
            *(uint4*)(d + 8192 + swA(srow, cb + 1)) = b1;
        }
        __syncthreads();
    }

    #pragma unroll
    for (int mi = 0; mi < 4; mi++) {
        const int row = m0 + wm + mi * 16 + grp;
        #pragma unroll
        for (int ni = 0; ni < 4; ni++) {
            const int col = n0 + wn + ni * 8 + tig * 2;
            const float bb0 = bias[col], bb1 = bias[col + 1];
            float c0 = acc[mi][ni][0] + bb0, c1 = acc[mi][ni][1] + bb1;
            float c2 = acc[mi][ni][2] + bb0, c3 = acc[mi][ni][3] + bb1;
            if (MODE == 1) {
                const int ii = (col & 63) >> 1;
                float sn = sp[row * 64 + ii], cs = sp[row * 64 + 32 + ii];
                float r0 = c0 * cs - c1 * sn, r1 = c1 * cs + c0 * sn;
                sn = sp[(row + 8) * 64 + ii]; cs = sp[(row + 8) * 64 + 32 + ii];
                float r2 = c2 * cs - c3 * sn, r3 = c3 * cs + c2 * sn;
                c0 = r0; c1 = r1; c2 = r2; c3 = r3;
            }
            *(__half2*)(C + (size_t)row * N + col)       = __floats2half2_rn(c0, c1);
            *(__half2*)(C + (size_t)(row + 8) * N + col) = __floats2half2_rn(c2, c3);
        }
    }
}

// ---------------------------------------------------------------------------
// scores GEMM (NT): per (b,n): S[q,k] = 0.125 * dot64(q_row, k_row), fp32 out.
// BM=128 BN=128 K=64 (single stage). grid (4,4,16)
// ---------------------------------------------------------------------------
__global__ __launch_bounds__(256)
void scores_kernel(const __half* __restrict__ q, const __half* __restrict__ k,
                   float* __restrict__ s)
{
    __shared__ __align__(16) unsigned char sm[32768];  // Q 16KB + K 16KB
    const uint32_t smBase = (uint32_t)__cvta_generic_to_shared(sm);

    const int z = blockIdx.z;              // b*8 + n
    const int b = z >> 3, n = z & 7;
    const size_t base = (size_t)b * 512 * 512 + n * 64;

    const int m0  = blockIdx.y * 128;
    const int n0k = blockIdx.x * 128;
    const int t   = threadIdx.x;

    const int srow = t >> 1;
    const int cb   = (t & 1) * 4;
    #pragma unroll
    for (int j = 0; j < 4; j++) {
        *(uint4*)(sm + swB8(srow, cb + j)) =
            *(const uint4*)(q + base + (size_t)(m0 + srow) * 512 + (cb + j) * 8);
        *(uint4*)(sm + 16384 + swB8(srow, cb + j)) =
            *(const uint4*)(k + base + (size_t)(n0k + srow) * 512 + (cb + j) * 8);
    }
    __syncthreads();

    const int wid  = t >> 5;
    const int wm   = (wid & 1) * 64;
    const int wn   = (wid >> 1) * 32;
    const int lane = t & 31;
    const int grp  = lane >> 2;
    const int tig  = lane & 3;

    const int aRow = wm + (lane & 15);
    const int aCs  = lane >> 4;
    const int bRow = wn + (lane & 7) + 8 * (lane >> 4);
    const int bCs  = (lane >> 3) & 1;

    float acc[4][4][4] = {};
    #pragma unroll
    for (int ks = 0; ks < 4; ks++) {
        uint32_t af[4][4], bf[2][4];
        #pragma unroll
        for (int mi = 0; mi < 4; mi++)
            ldsm4(af[mi], smBase + swB8(aRow + mi * 16, 2 * ks + aCs));
        #pragma unroll
        for (int nj = 0; nj < 2; nj++)
            ldsm4(bf[nj], smBase + 16384 + swB8(bRow + nj * 16, 2 * ks + bCs));
        #pragma unroll
        for (int mi = 0; mi < 4; mi++)
            #pragma unroll
            for (int ni = 0; ni < 4; ni++)
                mma16816(acc[mi][ni], af[mi], &bf[ni >> 1][(ni & 1) * 2]);
    }

    float* S = s + (size_t)z * 512 * 512;
    #pragma unroll
    for (int mi = 0; mi < 4; mi++) {
        const int row = m0 + wm + mi * 16 + grp;
        #pragma unroll
        for (int ni = 0; ni < 4; ni++) {
            const int col = n0k + wn + ni * 8 + tig * 2;
            *(float2*)(S + (size_t)row * 512 + col) =
                make_float2(acc[mi][ni][0] * 0.125f, acc[mi][ni][1] * 0.125f);
            *(float2*)(S + (size_t)(row + 8) * 512 + col) =
                make_float2(acc[mi][ni][2] * 0.125f, acc[mi][ni][3] * 0.125f);
        }
    }
}

// ---------------------------------------------------------------------------
// softmax: one warp per 512-score row -> half probs
// ---------------------------------------------------------------------------
__global__ __launch_bounds__(256)
void softmax_kernel(const float* __restrict__ s, __half* __restrict__ p)
{
    const int w    = threadIdx.x >> 5;
    const int lane = threadIdx.x & 31;
    const size_t row = (size_t)blockIdx.x * 8 + w;
    const float* src = s + row * 512;

    float4 v[4];
    float mx = -1e30f;
    #pragma unroll
    for (int j = 0; j < 4; j++) {
        v[j] = *(const float4*)(src + (lane + j * 32) * 4);
        mx = fmaxf(mx, fmaxf(fmaxf(v[j].x, v[j].y), fmaxf(v[j].z, v[j].w)));
    }
    #pragma unroll
    for (int off = 16; off; off >>= 1) mx = fmaxf(mx, __shfl_xor_sync(0xffffffffu, mx, off));

    float sum = 0.f;
    #pragma unroll
    for (int j = 0; j < 4; j++) {
        v[j].x = expf(v[j].x - mx); v[j].y = expf(v[j].y - mx);
        v[j].z = expf(v[j].z - mx); v[j].w = expf(v[j].w - mx);
        sum += v[j].x + v[j].y + v[j].z + v[j].w;
    }
    #pragma unroll
    for (int off = 16; off; off >>= 1) sum += __shfl_xor_sync(0xffffffffu, sum, off);
    const float inv = 1.f / sum;

    __half* dst = p + row * 512;
    #pragma unroll
    for (int j = 0; j < 4; j++) {
        uint2 u;
        u.x = pk2(v[j].x * inv, v[j].y * inv);
        u.y = pk2(v[j].z * inv, v[j].w * inv);
        *(uint2*)(dst + (lane + j * 32) * 4) = u;
    }
}

// ---------------------------------------------------------------------------
// ctx GEMM v2: per (b,n,r): V head-slice (512x64 half = 64KB) resident in smem,
// loop 4 m-tiles of P. BM=128 BN=64 BK=32; 8 warps (4m x 2n), warp 32x32.
// dynamic smem: V 64KB + A stages 16KB = 80KB
// ---------------------------------------------------------------------------
__global__ __launch_bounds__(256)
void h16_ctx(const __half* __restrict__ P, const __half* __restrict__ V,
             float* __restrict__ C)
{
    extern __shared__ __align__(16) unsigned char sm[];
    const uint32_t smBase = (uint32_t)__cvta_generic_to_shared(sm);

    const int z = blockIdx.x;                 // ((b*8+n)<<6) | r
    const int b = z >> 9, n = (z >> 6) & 7, r = z & 63;
    const int br = b * 64 + r;

    const __half* Vg = V + (size_t)br * (512 * 512) + n * 64;
    const __half* P0 = P + ((size_t)(b * 8 + n)) * (512 * 512);
    float*        Cc = C + (size_t)br * (512 * 512) + n * 64;

    const int t = threadIdx.x;

    // load V slice into smem (4096 uint4)
    for (int i = t; i < 4096; i += 256) {
        const int row = i >> 3, ch = i & 7;
        *(uint4*)(sm + swB8(row, ch)) = *(const uint4*)(Vg + (size_t)row * 512 + ch * 8);
    }
    __syncthreads();

    const int arow = t >> 1;
    const int acb  = (t & 1) * 2;

    const int wid  = t >> 5;
    const int wm   = (wid & 3) * 32;
    const int wn   = (wid >> 2) * 32;
    const int lane = t & 31;
    const int grp  = lane >> 2;
    const int tig  = lane & 3;

    const int aRow = wm + (lane & 15);
    const int aCs  = lane >> 4;
    const int bK   = (lane & 7) + 8 * ((lane >> 3) & 1);
    const int bCn  = (wn >> 3) + (lane >> 4);

    const uint32_t aStage = smBase + 65536;

    for (int mt = 0; mt < 4; mt++) {
        float acc[2][4][4] = {};
        const __half* Am = P0 + (size_t)(mt * 128 + arow) * 512 + acb * 8;

        uint4 u0 = *(const uint4*)(Am);
        uint4 u1 = *(const uint4*)(Am + 8);
        *(uint4*)(sm + 65536 + swA(arow, acb))     = u0;
        *(uint4*)(sm + 65536 + swA(arow, acb + 1)) = u1;
        __syncthreads();

        for (int it = 0; it < 16; it++) {
            const int s = it & 1;
            if (it + 1 < 16) {
                u0 = *(const uint4*)(Am + (it + 1) * 32);
                u1 = *(const uint4*)(Am + (it + 1) * 32 + 8);
            }
            const uint32_t bA = aStage + s * 8192;
            #pragma unroll
            for (int ks = 0; ks < 2; ks++) {
                uint32_t af[2][4], bf[2][4];
                #pragma unroll
                for (int mi = 0; mi < 2; mi++)
                    ldsm4(af[mi], bA + swA(aRow + mi * 16, 2 * ks + aCs));
                #pragma unroll
                for (int nj = 0; nj < 2; nj++)
                    ldsm4t(bf[nj], smBase + swB8(it * 32 + ks * 16 + bK, bCn + 2 * nj));
                #pragma unroll
                for (int mi = 0; mi < 2; mi++)
                    #pragma unroll
                    for (int ni = 0; ni < 4; ni++)
                        mma16816(acc[mi][ni], af[mi], &bf[ni >> 1][(ni & 1) * 2]);
            }
            if (it + 1 < 16) {
                unsigned char* d = sm + 65536 + (s ^ 1) * 8192;
                *(uint4*)(d + swA(arow, acb))     = u0;
                *(uint4*)(d + swA(arow, acb + 1)) = u1;
            }
            __syncthreads();
        }

        #pragma unroll
        for (int mi = 0; mi < 2; mi++) {
            const int row = mt * 128 + wm + mi * 16 + grp;
            #pragma unroll
            for (int ni = 0; ni < 4; ni++) {
                const int col = wn + ni * 8 + tig * 2;
                *(float2*)(Cc + (size_t)row * 512 + col) =
                    make_float2(acc[mi][ni][0], acc[mi][ni][1]);
                *(float2*)(Cc + (size_t)(row + 8) * 512 + col) =
                    make_float2(acc[mi][ni][2], acc[mi][ni][3]);
            }
        }
    }
}

// ---------------------------------------------------------------------------
extern "C" void kernel_launch(void* const* d_in, const int* in_sizes, int n_in,
                              void* d_out, int out_size)
{
    const float* hidden = (const float*)d_in[0];
    const float* sp     = (const float*)d_in[1];
    const float* Wq     = (const float*)d_in[2];
    const float* bq     = (const float*)d_in[3];
    const float* Wk     = (const float*)d_in[4];
    const float* bk     = (const float*)d_in[5];
    const float* Wv     = (const float*)d_in[6];
    const float* bv     = (const float*)d_in[7];
    float* out = (float*)d_out;
    (void)in_sizes; (void)n_in; (void)out_size;

    __half *hp, *wqp, *wkp, *wvp, *qp, *kp, *pp, *vp;
    float* spt;
    cudaGetSymbolAddress((void**)&hp,  g_h);
    cudaGetSymbolAddress((void**)&wqp, g_wq);
    cudaGetSymbolAddress((void**)&wkp, g_wk);
    cudaGetSymbolAddress((void**)&wvp, g_wv);
    cudaGetSymbolAddress((void**)&qp,  g_q);
    cudaGetSymbolAddress((void**)&kp,  g_k);
    cudaGetSymbolAddress((void**)&spt, g_s);
    cudaGetSymbolAddress((void**)&pp,  g_probs);
    cudaGetSymbolAddress((void**)&vp,  g_v);

    static bool attr_done = false;
    if (!attr_done) {
        cudaFuncSetAttribute(h16_ctx, cudaFuncAttributeMaxDynamicSharedMemorySize, 81920);
        attr_done = true;
    }

    dim3 blk(256);

    // convert hidden + weights to half
    f2h_kernel<<<4096, blk>>>(hidden, hp, (long)LB * LR * LL * LH);
    f2h_kernel<<<256, blk>>>(Wq, wqp, (long)LAH * LH);
    f2h_kernel<<<256, blk>>>(Wk, wkp, (long)LAH * LH);
    f2h_kernel<<<256, blk>>>(Wv, wvp, (long)LAH * LH);

    // fused Q/K projection + RoPE  (z = b*2 + which)
    h16_proj<1><<<dim3(4, 4, 4), blk>>>(hp, wqp, bq, qp, wkp, bk, kp, 512, 1024, sp);

    // V projection: M = 65536
    h16_proj<0><<<dim3(4, 512, 1), blk>>>(hp, wvp, bv, vp, nullptr, nullptr, nullptr, 512, 1024, nullptr);

    // scores (fp16 MMA) -> fp32, then softmax -> half probs
    scores_kernel<<<dim3(4, 4, 16), blk>>>(qp, kp, spt);
    softmax_kernel<<<1024, blk>>>(spt, pp);

    // ctx with V-resident smem
    h16_ctx<<<1024, blk, 81920>>>(pp, vp, out);
}

// round 5
// speedup vs baseline: 5.9851x; 1.1111x over previous
#include <cuda_runtime.h>
#include <cuda_fp16.h>
#include <cstdint>

#define LB 2
#define LR 64
#define LL 512
#define LH 1024
#define LAH 512

__device__ __half g_wq[LAH * LH], g_wk[LAH * LH], g_wv[LAH * LH];
__device__ __half g_q[(size_t)LB * LL * LAH];
__device__ __half g_k[(size_t)LB * LL * LAH];
__device__ float  g_s[(size_t)LB * 8 * LL * LL];
__device__ __half g_probs[(size_t)LB * 8 * LL * LL];
__device__ __half g_v[(size_t)LB * LR * LL * LAH];

// ---------------------------------------------------------------------------
__device__ __forceinline__ void ldsm4(uint32_t r[4], uint32_t a) {
    asm volatile("ldmatrix.sync.aligned.m8n8.x4.shared.b16 {%0,%1,%2,%3}, [%4];"
                 : "=r"(r[0]), "=r"(r[1]), "=r"(r[2]), "=r"(r[3]) : "r"(a));
}
__device__ __forceinline__ void ldsm4t(uint32_t r[4], uint32_t a) {
    asm volatile("ldmatrix.sync.aligned.m8n8.x4.trans.shared.b16 {%0,%1,%2,%3}, [%4];"
                 : "=r"(r[0]), "=r"(r[1]), "=r"(r[2]), "=r"(r[3]) : "r"(a));
}
__device__ __forceinline__ void mma16816(float c[4], const uint32_t a[4], const uint32_t b[2]) {
    asm volatile(
        "mma.sync.aligned.m16n8k16.row.col.f32.f16.f16.f32 "
        "{%0,%1,%2,%3}, {%4,%5,%6,%7}, {%8,%9}, {%0,%1,%2,%3};"
        : "+f"(c[0]), "+f"(c[1]), "+f"(c[2]), "+f"(c[3])
        : "r"(a[0]), "r"(a[1]), "r"(a[2]), "r"(a[3]), "r"(b[0]), "r"(b[1]));
}
__device__ __forceinline__ uint32_t pk2(float x, float y) {
    __half2 h = __floats2half2_rn(x, y);
    return *(uint32_t*)&h;
}
__device__ __forceinline__ uint4 cvt8(float4 a, float4 b) {
    uint4 u;
    u.x = pk2(a.x, a.y); u.y = pk2(a.z, a.w);
    u.z = pk2(b.x, b.y); u.w = pk2(b.z, b.w);
    return u;
}
// [rows][32-half] rows of 4x16B chunks, swizzle c ^ ((row>>1)&3)
__device__ __forceinline__ uint32_t swA(int row, int c) {
    return (uint32_t)((row * 4 + (c ^ ((row >> 1) & 3))) * 16);
}
// [rows][64-half] rows of 8x16B chunks, swizzle c ^ (row&7)
__device__ __forceinline__ uint32_t swB8(int row, int c) {
    return (uint32_t)((row * 8 + (c ^ (row & 7))) * 16);
}

// ---------------------------------------------------------------------------
// weights fp32 -> half (3 arrays in one launch): grid (256, 3)
// ---------------------------------------------------------------------------
__global__ void f2h3_kernel(const float* __restrict__ a, const float* __restrict__ b,
                            const float* __restrict__ c,
                            __half* __restrict__ da, __half* __restrict__ db,
                            __half* __restrict__ dc)
{
    const float* s; __half* d;
    if (blockIdx.y == 0)      { s = a; d = da; }
    else if (blockIdx.y == 1) { s = b; d = db; }
    else                      { s = c; d = dc; }
    const long j = ((long)blockIdx.x * 256 + threadIdx.x) * 8;
    float4 x = *(const float4*)(s + j);
    float4 y = *(const float4*)(s + j + 4);
    *(uint4*)(d + j) = cvt8(x, y);
}

// ---------------------------------------------------------------------------
// Q/K projection + RoPE (A fp32 in, half out).
// BM=128 BN=128 BK=32, 8 warps (2m x 4n). blockIdx.z = b*2 + which.
// ---------------------------------------------------------------------------
__global__ __launch_bounds__(256)
void qk_proj(const float* __restrict__ hidden,
             const __half* __restrict__ Bq, const float* __restrict__ bq, __half* __restrict__ Cq,
             const __half* __restrict__ Bk, const float* __restrict__ bk, __half* __restrict__ Ck,
             const float* __restrict__ sp)
{
    __shared__ __align__(16) unsigned char sm[2 * 16384];
    const uint32_t smBase = (uint32_t)__cvta_generic_to_shared(sm);

    const int b = blockIdx.z >> 1, which = blockIdx.z & 1;
    const float* A = hidden + (size_t)b * ((size_t)LR * LL * LH);
    const __half* B = which ? Bk : Bq;
    const float* bias = which ? bk : bq;
    __half* C = (which ? Ck : Cq) + (size_t)b * LL * LAH;

    const int m0 = blockIdx.y * 128;
    const int n0 = blockIdx.x * 128;
    const int t  = threadIdx.x;

    const int srow = t >> 1;
    const int cb   = (t & 1) * 2;
    const float* Ag = A + (size_t)(m0 + srow) * LH + cb * 8;
    const __half* Bg = B + (size_t)(n0 + srow) * LH + cb * 8;

    const int wid  = t >> 5;
    const int wm   = (wid & 1) * 64;
    const int wn   = (wid >> 1) * 32;
    const int lane = t & 31;
    const int grp  = lane >> 2;
    const int tig  = lane & 3;

    const int aRow = wm + (lane & 15);
    const int aCs  = lane >> 4;
    const int bRow = wn + (lane & 7) + 8 * (lane >> 4);
    const int bCs  = (lane >> 3) & 1;

    float acc[4][4][4] = {};

    float4 a00, a01, a10, a11;
    uint4 b0, b1;
    a00 = *(const float4*)(Ag);      a01 = *(const float4*)(Ag + 4);
    a10 = *(const float4*)(Ag + 8);  a11 = *(const float4*)(Ag + 12);
    b0 = *(const uint4*)(Bg);        b1 = *(const uint4*)(Bg + 8);
    *(uint4*)(sm + swA(srow, cb))            = cvt8(a00, a01);
    *(uint4*)(sm + swA(srow, cb + 1))        = cvt8(a10, a11);
    *(uint4*)(sm + 8192 + swA(srow, cb))     = b0;
    *(uint4*)(sm + 8192 + swA(srow, cb + 1)) = b1;
    __syncthreads();

    const int NK = LH / 32;
    for (int it = 0; it < NK; it++) {
        const int s = it & 1;
        if (it + 1 < NK) {
            const int k0 = (it + 1) * 32;
            a00 = *(const float4*)(Ag + k0);      a01 = *(const float4*)(Ag + k0 + 4);
            a10 = *(const float4*)(Ag + k0 + 8);  a11 = *(const float4*)(Ag + k0 + 12);
            b0 = *(const uint4*)(Bg + k0);        b1 = *(const uint4*)(Bg + k0 + 8);
        }
        const uint32_t bA = smBase + s * 16384;
        const uint32_t bB = bA + 8192;
        #pragma unroll
        for (int ks = 0; ks < 2; ks++) {
            uint32_t af[4][4], bf[2][4];
            #pragma unroll
            for (int mi = 0; mi < 4; mi++)
                ldsm4(af[mi], bA + swA(aRow + mi * 16, 2 * ks + aCs));
            #pragma unroll
            for (int nj = 0; nj < 2; nj++)
                ldsm4(bf[nj], bB + swA(bRow + nj * 16, 2 * ks + bCs));
            #pragma unroll
            for (int mi = 0; mi < 4; mi++)
                #pragma unroll
                for (int ni = 0; ni < 4; ni++)
                    mma16816(acc[mi][ni], af[mi], &bf[ni >> 1][(ni & 1) * 2]);
        }
        if (it + 1 < NK) {
            unsigned char* d = sm + (s ^ 1) * 16384;
            *(uint4*)(d + swA(srow, cb))            = cvt8(a00, a01);
            *(uint4*)(d + swA(srow, cb + 1))        = cvt8(a10, a11);
            *(uint4*)(d + 8192 + swA(srow, cb))     = b0;
            *(uint4*)(d + 8192 + swA(srow, cb + 1)) = b1;
        }
        __syncthreads();
    }

    #pragma unroll
    for (int mi = 0; mi < 4; mi++) {
        const int row = m0 + wm + mi * 16 + grp;
        #pragma unroll
        for (int ni = 0; ni < 4; ni++) {
            const int col = n0 + wn + ni * 8 + tig * 2;
            const float bb0 = bias[col], bb1 = bias[col + 1];
            float c0 = acc[mi][ni][0] + bb0, c1 = acc[mi][ni][1] + bb1;
            float c2 = acc[mi][ni][2] + bb0, c3 = acc[mi][ni][3] + bb1;
            const int ii = (col & 63) >> 1;
            float sn = sp[row * 64 + ii], cs = sp[row * 64 + 32 + ii];
            float r0 = c0 * cs - c1 * sn, r1 = c1 * cs + c0 * sn;
            sn = sp[(row + 8) * 64 + ii]; cs = sp[(row + 8) * 64 + 32 + ii];
            float r2 = c2 * cs - c3 * sn, r3 = c3 * cs + c2 * sn;
            *(__half2*)(C + (size_t)row * LAH + col)       = __floats2half2_rn(r0, r1);
            *(__half2*)(C + (size_t)(row + 8) * LAH + col) = __floats2half2_rn(r2, r3);
        }
    }
}

// ---------------------------------------------------------------------------
// V projection (A fp32 in, half out): C = hidden @ Wv^T + bv
// M=65536 N=512 K=1024. BM=64 BN=512 BK=32, 8 warps (2m x 4n), warp 32x128.
// A read exactly once from DRAM; W (1MB half) L2-resident.
// dynamic smem: 2 stages x (A 4KB + B 32KB) = 72KB
// ---------------------------------------------------------------------------
__global__ __launch_bounds__(256, 1)
void v_proj(const float* __restrict__ A, const __half* __restrict__ W,
            const float* __restrict__ bias, __half* __restrict__ C)
{
    extern __shared__ __align__(16) unsigned char sm[];
    const uint32_t smBase = (uint32_t)__cvta_generic_to_shared(sm);
    const int STAGE = 36864;

    const int m0 = blockIdx.x * 64;
    const int t  = threadIdx.x;
    const int lane = t & 31, wid = t >> 5;
    const int wm  = (wid & 1) * 32;
    const int wn  = (wid >> 1) * 128;
    const int grp = lane >> 2, tig = lane & 3;

    const int arow = t >> 2, ac = t & 3;
    const float* Ag = A + (size_t)(m0 + arow) * 1024 + ac * 8;
    const int bn0 = t >> 2, bc = t & 3;
    const __half* Wg = W + (size_t)bn0 * 1024 + bc * 8;

    const int aRow = wm + (lane & 15);
    const int aCs  = lane >> 4;
    const int bRow = wn + (lane & 7) + 8 * (lane >> 4);
    const int bCs  = (lane >> 3) & 1;

    float acc[2][16][4] = {};

    float4 pa0, pa1; uint4 pb[8];
    pa0 = *(const float4*)(Ag);
    pa1 = *(const float4*)(Ag + 4);
    #pragma unroll
    for (int j = 0; j < 8; j++) pb[j] = *(const uint4*)(Wg + (size_t)j * 64 * 1024);
    {
        unsigned char* d = sm;
        *(uint4*)(d + swA(arow, ac)) = cvt8(pa0, pa1);
        #pragma unroll
        for (int j = 0; j < 8; j++)
            *(uint4*)(d + 4096 + swA(bn0 + j * 64, bc)) = pb[j];
    }
    __syncthreads();

    for (int it = 0; it < 32; it++) {
        const int s = it & 1;
        if (it + 1 < 32) {
            const int k0 = (it + 1) * 32;
            pa0 = *(const float4*)(Ag + k0);
            pa1 = *(const float4*)(Ag + k0 + 4);
            #pragma unroll
            for (int j = 0; j < 8; j++)
                pb[j] = *(const uint4*)(Wg + (size_t)j * 64 * 1024 + k0);
        }
        const uint32_t bA = smBase + s * STAGE;
        const uint32_t bB = bA + 4096;
        #pragma unroll
        for (int ks = 0; ks < 2; ks++) {
            uint32_t af[2][4];
            ldsm4(af[0], bA + swA(aRow, 2 * ks + aCs));
            ldsm4(af[1], bA + swA(aRow + 16, 2 * ks + aCs));
            #pragma unroll
            for (int nj = 0; nj < 8; nj++) {
                uint32_t bf[4];
                ldsm4(bf, bB + swA(bRow + nj * 16, 2 * ks + bCs));
                mma16816(acc[0][2 * nj],     af[0], &bf[0]);
                mma16816(acc[0][2 * nj + 1], af[0], &bf[2]);
                mma16816(acc[1][2 * nj],     af[1], &bf[0]);
                mma16816(acc[1][2 * nj + 1], af[1], &bf[2]);
            }
        }
        if (it + 1 < 32) {
            unsigned char* d = sm + (s ^ 1) * STAGE;
            *(uint4*)(d + swA(arow, ac)) = cvt8(pa0, pa1);
            #pragma unroll
            for (int j = 0; j < 8; j++)
                *(uint4*)(d + 4096 + swA(bn0 + j * 64, bc)) = pb[j];
        }
        __syncthreads();
    }

    #pragma unroll
    for (int mi = 0; mi < 2; mi++) {
        const int row = m0 + wm + mi * 16 + grp;
        #pragma unroll
        for (int ni = 0; ni < 16; ni++) {
            const int col = wn + ni * 8 + tig * 2;
            const float b0 = bias[col], b1 = bias[col + 1];
            *(__half2*)(C + (size_t)row * 512 + col) =
                __floats2half2_rn(acc[mi][ni][0] + b0, acc[mi][ni][1] + b1);
            *(__half2*)(C + (size_t)(row + 8) * 512 + col) =
                __floats2half2_rn(acc[mi][ni][2] + b0, acc[mi][ni][3] + b1);
        }
    }
}

// ---------------------------------------------------------------------------
// scores GEMM (NT): per (b,n): S = 0.125 * q @ k^T, fp32 out. K=64 single stage.
// ---------------------------------------------------------------------------
__global__ __launch_bounds__(256)
void scores_kernel(const __half* __restrict__ q, const __half* __restrict__ k,
                   float* __restrict__ s)
{
    __shared__ __align__(16) unsigned char sm[32768];
    const uint32_t smBase = (uint32_t)__cvta_generic_to_shared(sm);

    const int z = blockIdx.z;
    const int b = z >> 3, n = z & 7;
    const size_t base = (size_t)b * 512 * 512 + n * 64;

    const int m0  = blockIdx.y * 128;
    const int n0k = blockIdx.x * 128;
    const int t   = threadIdx.x;

    const int srow = t >> 1;
    const int cb   = (t & 1) * 4;
    #pragma unroll
    for (int j = 0; j < 4; j++) {
        *(uint4*)(sm + swB8(srow, cb + j)) =
            *(const uint4*)(q + base + (size_t)(m0 + srow) * 512 + (cb + j) * 8);
        *(uint4*)(sm + 16384 + swB8(srow, cb + j)) =
            *(const uint4*)(k + base + (size_t)(n0k + srow) * 512 + (cb + j) * 8);
    }
    __syncthreads();

    const int wid  = t >> 5;
    const int wm   = (wid & 1) * 64;
    const int wn   = (wid >> 1) * 32;
    const int lane = t & 31;
    const int grp  = lane >> 2;
    const int tig  = lane & 3;

    const int aRow = wm + (lane & 15);
    const int aCs  = lane >> 4;
    const int bRow = wn + (lane & 7) + 8 * (lane >> 4);
    const int bCs  = (lane >> 3) & 1;

    float acc[4][4][4] = {};
    #pragma unroll
    for (int ks = 0; ks < 4; ks++) {
        uint32_t af[4][4], bf[2][4];
        #pragma unroll
        for (int mi = 0; mi < 4; mi++)
            ldsm4(af[mi], smBase + swB8(aRow + mi * 16, 2 * ks + aCs));
        #pragma unroll
        for (int nj = 0; nj < 2; nj++)
            ldsm4(bf[nj], smBase + 16384 + swB8(bRow + nj * 16, 2 * ks + bCs));
        #pragma unroll
        for (int mi = 0; mi < 4; mi++)
            #pragma unroll
            for (int ni = 0; ni < 4; ni++)
                mma16816(acc[mi][ni], af[mi], &bf[ni >> 1][(ni & 1) * 2]);
    }

    float* S = s + (size_t)z * 512 * 512;
    #pragma unroll
    for (int mi = 0; mi < 4; mi++) {
        const int row = m0 + wm + mi * 16 + grp;
        #pragma unroll
        for (int ni = 0; ni < 4; ni++) {
            const int col = n0k + wn + ni * 8 + tig * 2;
            *(float2*)(S + (size_t)row * 512 + col) =
                make_float2(acc[mi][ni][0] * 0.125f, acc[mi][ni][1] * 0.125f);
            *(float2*)(S + (size_t)(row + 8) * 512 + col) =
                make_float2(acc[mi][ni][2] * 0.125f, acc[mi][ni][3] * 0.125f);
        }
    }
}

// ---------------------------------------------------------------------------
// softmax: one warp per 512-score row -> half probs
// ---------------------------------------------------------------------------
__global__ __launch_bounds__(256)
void softmax_kernel(const float* __restrict__ s, __half* __restrict__ p)
{
    const int w    = threadIdx.x >> 5;
    const int lane = threadIdx.x & 31;
    const size_t row = (size_t)blockIdx.x * 8 + w;
    const float* src = s + row * 512;

    float4 v[4];
    float mx = -1e30f;
    #pragma unroll
    for (int j = 0; j < 4; j++) {
        v[j] = *(const float4*)(src + (lane + j * 32) * 4);
        mx = fmaxf(mx, fmaxf(fmaxf(v[j].x, v[j].y), fmaxf(v[j].z, v[j].w)));
    }
    #pragma unroll
    for (int off = 16; off; off >>= 1) mx = fmaxf(mx, __shfl_xor_sync(0xffffffffu, mx, off));

    float sum = 0.f;
    #pragma unroll
    for (int j = 0; j < 4; j++) {
        v[j].x = expf(v[j].x - mx); v[j].y = expf(v[j].y - mx);
        v[j].z = expf(v[j].z - mx); v[j].w = expf(v[j].w - mx);
        sum += v[j].x + v[j].y + v[j].z + v[j].w;
    }
    #pragma unroll
    for (int off = 16; off; off >>= 1) sum += __shfl_xor_sync(0xffffffffu, sum, off);
    const float inv = 1.f / sum;

    __half* dst = p + row * 512;
    #pragma unroll
    for (int j = 0; j < 4; j++) {
        uint2 u;
        u.x = pk2(v[j].x * inv, v[j].y * inv);
        u.y = pk2(v[j].z * inv, v[j].w * inv);
        *(uint2*)(dst + (lane + j * 32) * 4) = u;
    }
}

// ---------------------------------------------------------------------------
// ctx GEMM: per (b,n,r): V head-slice (512x64 half = 64KB) resident in smem,
// loop 4 m-tiles of P. BM=128 BN=64 BK=32; 8 warps (4m x 2n), warp 32x32.
// dynamic smem 80KB.
// ---------------------------------------------------------------------------
__global__ __launch_bounds__(256)
void h16_ctx(const __half* __restrict__ P, const __half* __restrict__ V,
             float* __restrict__ C)
{
    extern __shared__ __align__(16) unsigned char sm[];
    const uint32_t smBase = (uint32_t)__cvta_generic_to_shared(sm);

    const int z = blockIdx.x;
    const int b = z >> 9, n = (z >> 6) & 7, r = z & 63;
    const int br = b * 64 + r;

    const __half* Vg = V + (size_t)br * (512 * 512) + n * 64;
    const __half* P0 = P + ((size_t)(b * 8 + n)) * (512 * 512);
    float*        Cc = C + (size_t)br * (512 * 512) + n * 64;

    const int t = threadIdx.x;

    for (int i = t; i < 4096; i += 256) {
        const int row = i >> 3, ch = i & 7;
        *(uint4*)(sm + swB8(row, ch)) = *(const uint4*)(Vg + (size_t)row * 512 + ch * 8);
    }
    __syncthreads();

    const int arow = t >> 1;
    const int acb  = (t & 1) * 2;

    const int wid  = t >> 5;
    const int wm   = (wid & 3) * 32;
    const int wn   = (wid >> 2) * 32;
    const int lane = t & 31;
    const int grp  = lane >> 2;
    const int tig  = lane & 3;

    const int aRow = wm + (lane & 15);
    const int aCs  = lane >> 4;
    const int bK   = (lane & 7) + 8 * ((lane >> 3) & 1);
    const int bCn  = (wn >> 3) + (lane >> 4);

    const uint32_t aStage = smBase + 65536;

    for (int mt = 0; mt < 4; mt++) {
        float acc[2][4][4] = {};
        const __half* Am = P0 + (size_t)(mt * 128 + arow) * 512 + acb * 8;

        uint4 u0 = *(const uint4*)(Am);
        uint4 u1 = *(const uint4*)(Am + 8);
        *(uint4*)(sm + 65536 + swA(arow, acb))     = u0;
        *(uint4*)(sm + 65536 + swA(arow, acb + 1)) = u1;
        __syncthreads();

        for (int it = 0; it < 16; it++) {
            const int s = it & 1;
            if (it + 1 < 16) {
                u0 = *(const uint4*)(Am + (it + 1) * 32);
                u1 = *(const uint4*)(Am + (it + 1) * 32 + 8);
            }
            const uint32_t bA = aStage + s * 8192;
            #pragma unroll
            for (int ks = 0; ks < 2; ks++) {
                uint32_t af[2][4], bf[2][4];
                #pragma unroll
                for (int mi = 0; mi < 2; mi++)
                    ldsm4(af[mi], bA + swA(aRow + mi * 16, 2 * ks + aCs));
                #pragma unroll
                for (int nj = 0; nj < 2; nj++)
                    ldsm4t(bf[nj], smBase + swB8(it * 32 + ks * 16 + bK, bCn + 2 * nj));
                #pragma unroll
                for (int mi = 0; mi < 2; mi++)
                    #pragma unroll
                    for (int ni = 0; ni < 4; ni++)
                        mma16816(acc[mi][ni], af[mi], &bf[ni >> 1][(ni & 1) * 2]);
            }
            if (it + 1 < 16) {
                unsigned char* d = sm + 65536 + (s ^ 1) * 8192;
                *(uint4*)(d + swA(arow, acb))     = u0;
                *(uint4*)(d + swA(arow, acb + 1)) = u1;
            }
            __syncthreads();
        }

        #pragma unroll
        for (int mi = 0; mi < 2; mi++) {
            const int row = mt * 128 + wm + mi * 16 + grp;
            #pragma unroll
            for (int ni = 0; ni < 4; ni++) {
                const int col = wn + ni * 8 + tig * 2;
                *(float2*)(Cc + (size_t)row * 512 + col) =
                    make_float2(acc[mi][ni][0], acc[mi][ni][1]);
                *(float2*)(Cc + (size_t)(row + 8) * 512 + col) =
                    make_float2(acc[mi][ni][2], acc[mi][ni][3]);
            }
        }
    }
}

// ---------------------------------------------------------------------------
extern "C" void kernel_launch(void* const* d_in, const int* in_sizes, int n_in,
                              void* d_out, int out_size)
{
    const float* hidden = (const float*)d_in[0];
    const float* sp     = (const float*)d_in[1];
    const float* Wq     = (const float*)d_in[2];
    const float* bq     = (const float*)d_in[3];
    const float* Wk     = (const float*)d_in[4];
    const float* bk     = (const float*)d_in[5];
    const float* Wv     = (const float*)d_in[6];
    const float* bv     = (const float*)d_in[7];
    float* out = (float*)d_out;
    (void)in_sizes; (void)n_in; (void)out_size;

    __half *wqp, *wkp, *wvp, *qp, *kp, *pp, *vp;
    float* spt;
    cudaGetSymbolAddress((void**)&wqp, g_wq);
    cudaGetSymbolAddress((void**)&wkp, g_wk);
    cudaGetSymbolAddress((void**)&wvp, g_wv);
    cudaGetSymbolAddress((void**)&qp,  g_q);
    cudaGetSymbolAddress((void**)&kp,  g_k);
    cudaGetSymbolAddress((void**)&spt, g_s);
    cudaGetSymbolAddress((void**)&pp,  g_probs);
    cudaGetSymbolAddress((void**)&vp,  g_v);

    static bool attr_done = false;
    if (!attr_done) {
        cudaFuncSetAttribute(h16_ctx, cudaFuncAttributeMaxDynamicSharedMemorySize, 81920);
        cudaFuncSetAttribute(v_proj, cudaFuncAttributeMaxDynamicSharedMemorySize, 73728);
        attr_done = true;
    }

    dim3 blk(256);

    // weights fp32 -> half (one small launch)
    f2h3_kernel<<<dim3(256, 3), blk>>>(Wq, Wk, Wv, wqp, wkp, wvp);

    // Q/K projection + RoPE directly from fp32 hidden (row 0 slices)
    qk_proj<<<dim3(4, 4, 4), blk>>>(hidden, wqp, bq, qp, wkp, bk, kp, sp);

    // V projection: fp32 hidden read once, BN=512
    v_proj<<<dim3(1024), blk, 73728>>>(hidden, wvp, bv, vp);

    // scores + softmax
    scores_kernel<<<dim3(4, 4, 16), blk>>>(qp, kp, spt);
    softmax_kernel<<<1024, blk>>>(spt, pp);

    // ctx with V-resident smem
    h16_ctx<<<1024, blk, 81920>>>(pp, vp, out);
}

// round 7
// speedup vs baseline: 6.8756x; 1.1488x over previous
#include <cuda_runtime.h>
#include <cuda_fp16.h>
#include <cstdint>

#define LB 2
#define LR 64
#define LL 512
#define LH 1024
#define LAH 512

__device__ __half g_wq[LAH * LH], g_wk[LAH * LH], g_wv[LAH * LH];
__device__ __half g_q[(size_t)LB * LL * LAH];
__device__ __half g_k[(size_t)LB * LL * LAH];
__device__ float  g_s[(size_t)LB * 8 * LL * LL];
__device__ __half g_probs[(size_t)LB * 8 * LL * LL];
__device__ __half g_v[(size_t)LB * LR * LL * LAH];

// ---------------------------------------------------------------------------
__device__ __forceinline__ void ldsm4(uint32_t r[4], uint32_t a) {
    asm volatile("ldmatrix.sync.aligned.m8n8.x4.shared.b16 {%0,%1,%2,%3}, [%4];"
                 : "=r"(r[0]), "=r"(r[1]), "=r"(r[2]), "=r"(r[3]) : "r"(a));
}
__device__ __forceinline__ void ldsm4t(uint32_t r[4], uint32_t a) {
    asm volatile("ldmatrix.sync.aligned.m8n8.x4.trans.shared.b16 {%0,%1,%2,%3}, [%4];"
                 : "=r"(r[0]), "=r"(r[1]), "=r"(r[2]), "=r"(r[3]) : "r"(a));
}
__device__ __forceinline__ void mma16816(float c[4], const uint32_t a[4], const uint32_t b[2]) {
    asm volatile(
        "mma.sync.aligned.m16n8k16.row.col.f32.f16.f16.f32 "
        "{%0,%1,%2,%3}, {%4,%5,%6,%7}, {%8,%9}, {%0,%1,%2,%3};"
        : "+f"(c[0]), "+f"(c[1]), "+f"(c[2]), "+f"(c[3])
        : "r"(a[0]), "r"(a[1]), "r"(a[2]), "r"(a[3]), "r"(b[0]), "r"(b[1]));
}
__device__ __forceinline__ uint32_t pk2(float x, float y) {
    __half2 h = __floats2half2_rn(x, y);
    return *(uint32_t*)&h;
}
__device__ __forceinline__ uint4 cvt8(float4 a, float4 b) {
    uint4 u;
    u.x = pk2(a.x, a.y); u.y = pk2(a.z, a.w);
    u.z = pk2(b.x, b.y); u.w = pk2(b.z, b.w);
    return u;
}
// [rows][32-half] rows of 4x16B chunks, swizzle c ^ ((row>>1)&3)
__device__ __forceinline__ uint32_t swA(int row, int c) {
    return (uint32_t)((row * 4 + (c ^ ((row >> 1) & 3))) * 16);
}
// [rows][64-half] rows of 8x16B chunks (128B rows), SW128: c ^ (row&7)
__device__ __forceinline__ uint32_t swB8(int row, int c) {
    return (uint32_t)((row * 8 + (c ^ (row & 7))) * 16);
}
// cp.async 16B
__device__ __forceinline__ void cpa16(uint32_t dst, const void* src) {
    asm volatile("cp.async.cg.shared.global [%0], [%1], 16;" :: "r"(dst), "l"(src));
}
__device__ __forceinline__ void cpa_commit() {
    asm volatile("cp.async.commit_group;" ::: "memory");
}
template<int N>
__device__ __forceinline__ void cpa_wait() {
    asm volatile("cp.async.wait_group %0;" :: "n"(N) : "memory");
}

// ---------------------------------------------------------------------------
// weights fp32 -> half (3 arrays in one launch): grid (256, 3)
// ---------------------------------------------------------------------------
__global__ void f2h3_kernel(const float* __restrict__ a, const float* __restrict__ b,
                            const float* __restrict__ c,
                            __half* __restrict__ da, __half* __restrict__ db,
                            __half* __restrict__ dc)
{
    const float* s; __half* d;
    if (blockIdx.y == 0)      { s = a; d = da; }
    else if (blockIdx.y == 1) { s = b; d = db; }
    else                      { s = c; d = dc; }
    const long j = ((long)blockIdx.x * 256 + threadIdx.x) * 8;
    float4 x = *(const float4*)(s + j);
    float4 y = *(const float4*)(s + j + 4);
    *(uint4*)(d + j) = cvt8(x, y);
}

// ---------------------------------------------------------------------------
// V projection: C = hidden @ Wv^T + bv (half out)
// M=65536 N=512 K=1024. BM=64, BN=512, BK=32. 8 warps, warp 32x128.
// 3-stage pipeline: B via cp.async, A via register staging (fp32->half).
// stage = A 4KB + B 32KB = 36KB; 3 stages = 108KB dynamic smem.
// ---------------------------------------------------------------------------
__global__ __launch_bounds__(256, 1)
void v_proj(const float* __restrict__ A, const __half* __restrict__ W,
            const float* __restrict__ bias, __half* __restrict__ C)
{
    extern __shared__ __align__(16) unsigned char sm[];
    const uint32_t smBase = (uint32_t)__cvta_generic_to_shared(sm);
    const int STAGE = 36864;

    const int m0 = blockIdx.x * 64;
    const int t  = threadIdx.x;
    const int lane = t & 31, wid = t >> 5;
    const int wm  = (wid & 1) * 32;
    const int wn  = (wid >> 1) * 128;
    const int grp = lane >> 2, tig = lane & 3;

    const int arow = t >> 2, ac = t & 3;
    const float* Ag = A + (size_t)(m0 + arow) * 1024 + ac * 8;
    const int bn0 = t >> 2, bc = t & 3;
    const __half* Wg = W + (size_t)bn0 * 1024 + bc * 8;

    const int aRow = wm + (lane & 15);
    const int aCs  = lane >> 4;
    const int bRow = wn + (lane & 7) + 8 * (lane >> 4);
    const int bCs  = (lane >> 3) & 1;

    float acc[2][16][4] = {};

    // prologue: stages 0,1
    #pragma unroll
    for (int p = 0; p < 2; p++) {
        const int k0 = p * 32;
        const uint32_t st = smBase + p * STAGE;
        #pragma unroll
        for (int j = 0; j < 8; j++)
            cpa16(st + 4096 + swA(bn0 + j * 64, bc), Wg + (size_t)j * 64 * 1024 + k0);
        float4 x = *(const float4*)(Ag + k0);
        float4 y = *(const float4*)(Ag + k0 + 4);
        *(uint4*)(sm + p * STAGE + swA(arow, ac)) = cvt8(x, y);
        cpa_commit();
    }

    for (int it = 0; it < 32; it++) {
        const int s = it - (it / 3) * 3;
        cpa_wait<1>();
        __syncthreads();

        // prefetch stage it+2
        float4 px, py;
        const bool pf = (it + 2 < 32);
        const int s2 = (it + 2) - ((it + 2) / 3) * 3;
        if (pf) {
            const int k0 = (it + 2) * 32;
            const uint32_t st = smBase + s2 * STAGE;
            #pragma unroll
            for (int j = 0; j < 8; j++)
                cpa16(st + 4096 + swA(bn0 + j * 64, bc), Wg + (size_t)j * 64 * 1024 + k0);
            px = *(const float4*)(Ag + k0);
            py = *(const float4*)(Ag + k0 + 4);
        }

        const uint32_t bA = smBase + s * STAGE;
        const uint32_t bB = bA + 4096;
        #pragma unroll
        for (int ks = 0; ks < 2; ks++) {
            uint32_t af[2][4];
            ldsm4(af[0], bA + swA(aRow, 2 * ks + aCs));
            ldsm4(af[1], bA + swA(aRow + 16, 2 * ks + aCs));
            #pragma unroll
            for (int nj = 0; nj < 8; nj++) {
                uint32_t bf[4];
                ldsm4(bf, bB + swA(bRow + nj * 16, 2 * ks + bCs));
                mma16816(acc[0][2 * nj],     af[0], &bf[0]);
                mma16816(acc[0][2 * nj + 1], af[0], &bf[2]);
                mma16816(acc[1][2 * nj],     af[1], &bf[0]);
                mma16816(acc[1][2 * nj + 1], af[1], &bf[2]);
            }
        }

        if (pf) {
            *(uint4*)(sm + s2 * STAGE + swA(arow, ac)) = cvt8(px, py);
            cpa_commit();
        } else {
            cpa_commit();  // keep group count in lockstep
        }
    }

    #pragma unroll
    for (int mi = 0; mi < 2; mi++) {
        const int row = m0 + wm + mi * 16 + grp;
        #pragma unroll
        for (int ni = 0; ni < 16; ni++) {
            const int col = wn + ni * 8 + tig * 2;
            const float b0 = bias[col], b1 = bias[col + 1];
            *(__half2*)(C + (size_t)row * 512 + col) =
                __floats2half2_rn(acc[mi][ni][0] + b0, acc[mi][ni][1] + b1);
            *(__half2*)(C + (size_t)(row + 8) * 512 + col) =
                __floats2half2_rn(acc[mi][ni][2] + b0, acc[mi][ni][3] + b1);
        }
    }
}

// ---------------------------------------------------------------------------
// Q/K projection + RoPE (A fp32 in, half out)
// ---------------------------------------------------------------------------
__global__ __launch_bounds__(256)
void qk_proj(const float* __restrict__ hidden,
             const __half* __restrict__ Bq, const float* __restrict__ bq, __half* __restrict__ Cq,
             const __half* __restrict__ Bk, const float* __restrict__ bk, __half* __restrict__ Ck,
             const float* __restrict__ sp)
{
    __shared__ __align__(16) unsigned char sm[2 * 16384];
    const uint32_t smBase = (uint32_t)__cvta_generic_to_shared(sm);

    const int b = blockIdx.z >> 1, which = blockIdx.z & 1;
    const float* A = hidden + (size_t)b * ((size_t)LR * LL * LH);
    const __half* B = which ? Bk : Bq;
    const float* bias = which ? bk : bq;
    __half* C = (which ? Ck : Cq) + (size_t)b * LL * LAH;

    const int m0 = blockIdx.y * 128;
    const int n0 = blockIdx.x * 128;
    const int t  = threadIdx.x;

    const int srow = t >> 1;
    const int cb   = (t & 1) * 2;
    const float* Ag = A + (size_t)(m0 + srow) * LH + cb * 8;
    const __half* Bg = B + (size_t)(n0 + srow) * LH + cb * 8;

    const int wid  = t >> 5;
    const int wm   = (wid & 1) * 64;
    const int wn   = (wid >> 1) * 32;
    const int lane = t & 31;
    const int grp  = lane >> 2;
    const int tig  = lane & 3;

    const int aRow = wm + (lane & 15);
    const int aCs  = lane >> 4;
    const int bRow = wn + (lane & 7) + 8 * (lane >> 4);
    const int bCs  = (lane >> 3) & 1;

    float acc[4][4][4] = {};

    float4 a00, a01, a10, a11;
    uint4 b0, b1;
    a00 = *(const float4*)(Ag);      a01 = *(const float4*)(Ag + 4);
    a10 = *(const float4*)(Ag + 8);  a11 = *(const float4*)(Ag + 12);
    b0 = *(const uint4*)(Bg);        b1 = *(const uint4*)(Bg + 8);
    *(uint4*)(sm + swA(srow, cb))            = cvt8(a00, a01);
    *(uint4*)(sm + swA(srow, cb + 1))        = cvt8(a10, a11);
    *(uint4*)(sm + 8192 + swA(srow, cb))     = b0;
    *(uint4*)(sm + 8192 + swA(srow, cb + 1)) = b1;
    __syncthreads();

    const int NK = LH / 32;
    for (int it = 0; it < NK; it++) {
        const int s = it & 1;
        if (it + 1 < NK) {
            const int k0 = (it + 1) * 32;
            a00 = *(const float4*)(Ag + k0);      a01 = *(const float4*)(Ag + k0 + 4);
            a10 = *(const float4*)(Ag + k0 + 8);  a11 = *(const float4*)(Ag + k0 + 12);
            b0 = *(const uint4*)(Bg + k0);        b1 = *(const uint4*)(Bg + k0 + 8);
        }
        const uint32_t bA = smBase + s * 16384;
        const uint32_t bB = bA + 8192;
        #pragma unroll
        for (int ks = 0; ks < 2; ks++) {
            uint32_t af[4][4], bf[2][4];
            #pragma unroll
            for (int mi = 0; mi < 4; mi++)
                ldsm4(af[mi], bA + swA(aRow + mi * 16, 2 * ks + aCs));
            #pragma unroll
            for (int nj = 0; nj < 2; nj++)
                ldsm4(bf[nj], bB + swA(bRow + nj * 16, 2 * ks + bCs));
            #pragma unroll
            for (int mi = 0; mi < 4; mi++)
                #pragma unroll
                for (int ni = 0; ni < 4; ni++)
                    mma16816(acc[mi][ni], af[mi], &bf[ni >> 1][(ni & 1) * 2]);
        }
        if (it + 1 < NK) {
            unsigned char* d = sm + (s ^ 1) * 16384;
            *(uint4*)(d + swA(srow, cb))            = cvt8(a00, a01);
            *(uint4*)(d + swA(srow, cb + 1))        = cvt8(a10, a11);
            *(uint4*)(d + 8192 + swA(srow, cb))     = b0;
            *(uint4*)(d + 8192 + swA(srow, cb + 1)) = b1;
        }
        __syncthreads();
    }

    #pragma unroll
    for (int mi = 0; mi < 4; mi++) {
        const int row = m0 + wm + mi * 16 + grp;
        #pragma unroll
        for (int ni = 0; ni < 4; ni++) {
            const int col = n0 + wn + ni * 8 + tig * 2;
            const float bb0 = bias[col], bb1 = bias[col + 1];
            float c0 = acc[mi][ni][0] + bb0, c1 = acc[mi][ni][1] + bb1;
            float c2 = acc[mi][ni][2] + bb0, c3 = acc[mi][ni][3] + bb1;
            const int ii = (col & 63) >> 1;
            float sn = sp[row * 64 + ii], cs = sp[row * 64 + 32 + ii];
            float r0 = c0 * cs - c1 * sn, r1 = c1 * cs + c0 * sn;
            sn = sp[(row + 8) * 64 + ii]; cs = sp[(row + 8) * 64 + 32 + ii];
            float r2 = c2 * cs - c3 * sn, r3 = c3 * cs + c2 * sn;
            *(__half2*)(C + (size_t)row * LAH + col)       = __floats2half2_rn(r0, r1);
            *(__half2*)(C + (size_t)(row + 8) * LAH + col) = __floats2half2_rn(r2, r3);
        }
    }
}

// ---------------------------------------------------------------------------
// scores GEMM (NT): per (b,n): S = 0.125 * q @ k^T, fp32 out. K=64 single stage.
// ---------------------------------------------------------------------------
__global__ __launch_bounds__(256)
void scores_kernel(const __half* __restrict__ q, const __half* __restrict__ k,
                   float* __restrict__ s)
{
    __shared__ __align__(16) unsigned char sm[32768];
    const uint32_t smBase = (uint32_t)__cvta_generic_to_shared(sm);

    const int z = blockIdx.z;
    const int b = z >> 3, n = z & 7;
    const size_t base = (size_t)b * 512 * 512 + n * 64;

    const int m0  = blockIdx.y * 128;
    const int n0k = blockIdx.x * 128;
    const int t   = threadIdx.x;

    const int srow = t >> 1;
    const int cb   = (t & 1) * 4;
    #pragma unroll
    for (int j = 0; j < 4; j++) {
        cpa16(smBase + swB8(srow, cb + j),
              q + base + (size_t)(m0 + srow) * 512 + (cb + j) * 8);
        cpa16(smBase + 16384 + swB8(srow, cb + j),
              k + base + (size_t)(n0k + srow) * 512 + (cb + j) * 8);
    }
    cpa_commit();
    cpa_wait<0>();
    __syncthreads();

    const int wid  = t >> 5;
    const int wm   = (wid & 1) * 64;
    const int wn   = (wid >> 1) * 32;
    const int lane = t & 31;
    const int grp  = lane >> 2;
    const int tig  = lane & 3;

    const int aRow = wm + (lane & 15);
    const int aCs  = lane >> 4;
    const int bRow = wn + (lane & 7) + 8 * (lane >> 4);
    const int bCs  = (lane >> 3) & 1;

    float acc[4][4][4] = {};
    #pragma unroll
    for (int ks = 0; ks < 4; ks++) {
        uint32_t af[4][4], bf[2][4];
        #pragma unroll
        for (int mi = 0; mi < 4; mi++)
            ldsm4(af[mi], smBase + swB8(aRow + mi * 16, 2 * ks + aCs));
        #pragma unroll
        for (int nj = 0; nj < 2; nj++)
            ldsm4(bf[nj], smBase + 16384 + swB8(bRow + nj * 16, 2 * ks + bCs));
        #pragma unroll
        for (int mi = 0; mi < 4; mi++)
            #pragma unroll
            for (int ni = 0; ni < 4; ni++)
                mma16816(acc[mi][ni], af[mi], &bf[ni >> 1][(ni & 1) * 2]);
    }

    float* S = s + (size_t)z * 512 * 512;
    #pragma unroll
    for (int mi = 0; mi < 4; mi++) {
        const int row = m0 + wm + mi * 16 + grp;
        #pragma unroll
        for (int ni = 0; ni < 4; ni++) {
            const int col = n0k + wn + ni * 8 + tig * 2;
            *(float2*)(S + (size_t)row * 512 + col) =
                make_float2(acc[mi][ni][0] * 0.125f, acc[mi][ni][1] * 0.125f);
            *(float2*)(S + (size_t)(row + 8) * 512 + col) =
                make_float2(acc[mi][ni][2] * 0.125f, acc[mi][ni][3] * 0.125f);
        }
    }
}

// ---------------------------------------------------------------------------
// softmax: one warp per 512-score row -> half probs
// ---------------------------------------------------------------------------
__global__ __launch_bounds__(256)
void softmax_kernel(const float* __restrict__ s, __half* __restrict__ p)
{
    const int w    = threadIdx.x >> 5;
    const int lane = threadIdx.x & 31;
    const size_t row = (size_t)blockIdx.x * 8 + w;
    const float* src = s + row * 512;

    float4 v[4];
    float mx = -1e30f;
    #pragma unroll
    for (int j = 0; j < 4; j++) {
        v[j] = *(const float4*)(src + (lane + j * 32) * 4);
        mx = fmaxf(mx, fmaxf(fmaxf(v[j].x, v[j].y), fmaxf(v[j].z, v[j].w)));
    }
    #pragma unroll
    for (int off = 16; off; off >>= 1) mx = fmaxf(mx, __shfl_xor_sync(0xffffffffu, mx, off));

    float sum = 0.f;
    #pragma unroll
    for (int j = 0; j < 4; j++) {
        v[j].x = expf(v[j].x - mx); v[j].y = expf(v[j].y - mx);
        v[j].z = expf(v[j].z - mx); v[j].w = expf(v[j].w - mx);
        sum += v[j].x + v[j].y + v[j].z + v[j].w;
    }
    #pragma unroll
    for (int off = 16; off; off >>= 1) sum += __shfl_xor_sync(0xffffffffu, sum, off);
    const float inv = 1.f / sum;

    __half* dst = p + row * 512;
    #pragma unroll
    for (int j = 0; j < 4; j++) {
        uint2 u;
        u.x = pk2(v[j].x * inv, v[j].y * inv);
        u.y = pk2(v[j].z * inv, v[j].w * inv);
        *(uint2*)(dst + (lane + j * 32) * 4) = u;
    }
}

// ---------------------------------------------------------------------------
// ctx GEMM: per (b,n,r): V head-slice (512x64 half = 64KB) resident in smem,
// flattened 64-iter cp.async pipeline over (mt, it). BM=128 BN=64 BK=32.
// smem: V 64KB + 3 x 8KB A stages = 88KB.
// ---------------------------------------------------------------------------
__global__ __launch_bounds__(256)
void h16_ctx(const __half* __restrict__ P, const __half* __restrict__ V,
             float* __restrict__ C)
{
    extern __shared__ __align__(16) unsigned char sm[];
    const uint32_t smBase = (uint32_t)__cvta_generic_to_shared(sm);

    const int z = blockIdx.x;
    const int b = z >> 9, n = (z >> 6) & 7, r = z & 63;
    const int br = b * 64 + r;

    const __half* Vg = V + (size_t)br * (512 * 512) + n * 64;
    const __half* P0 = P + ((size_t)(b * 8 + n)) * (512 * 512);
    float*        Cc = C + (size_t)br * (512 * 512) + n * 64;

    const int t = threadIdx.x;

    // V preload via cp.async (group 0)
    #pragma unroll
    for (int j = 0; j < 16; j++) {
        const int i = t + 256 * j;
        const int row = i >> 3, ch = i & 7;
        cpa16(smBase + swB8(row, ch), Vg + (size_t)row * 512 + ch * 8);
    }
    cpa_commit();

    const int arow = t >> 1;
    const int acb  = (t & 1) * 2;
    const uint32_t aOff = swA(arow, acb);  // two consecutive chunks: acb, acb+1

    // prefetch flat iters 0,1 (A stages): flat f -> mt=f>>4, it=f&15
    #pragma unroll
    for (int p = 0; p < 2; p++) {
        const uint32_t st = smBase + 65536 + p * 8192;
        const __half* Am = P0 + (size_t)((p >> 4) * 128 + arow) * 512 + (p & 15) * 32 + acb * 8;
        cpa16(st + swA(arow, acb), Am);
        cpa16(st + swA(arow, acb + 1), Am + 8);
        cpa_commit();
    }

    const int wid  = t >> 5;
    const int wm   = (wid & 3) * 32;
    const int wn   = (wid >> 2) * 32;
    const int lane = t & 31;
    const int grp  = lane >> 2;
    const int tig  = lane & 3;

    const int aRow = wm + (lane & 15);
    const int aCs  = lane >> 4;
    const int bK   = (lane & 7) + 8 * ((lane >> 3) & 1);
    const int bCn  = (wn >> 3) + (lane >> 4);

    float acc[2][4][4] = {};

    for (int f = 0; f < 64; f++) {
        const int s = f - (f / 3) * 3;
        const int it = f & 15;
        cpa_wait<1>();
        __syncthreads();

        // prefetch flat f+2
        if (f + 2 < 64) {
            const int f2 = f + 2;
            const int s2 = f2 - (f2 / 3) * 3;
            const uint32_t st = smBase + 65536 + s2 * 8192;
            const __half* Am = P0 + (size_t)((f2 >> 4) * 128 + arow) * 512 + (f2 & 15) * 32 + acb * 8;
            cpa16(st + swA(arow, acb), Am);
            cpa16(st + swA(arow, acb + 1), Am + 8);
        }
        cpa_commit();

        const uint32_t bA = smBase + 65536 + s * 8192;
        #pragma unroll
        for (int ks = 0; ks < 2; ks++) {
            uint32_t af[2][4], bf[2][4];
            #pragma unroll
            for (int mi = 0; mi < 2; mi++)
                ldsm4(af[mi], bA + swA(aRow + mi * 16, 2 * ks + aCs));
            #pragma unroll
            for (int nj = 0; nj < 2; nj++)
                ldsm4t(bf[nj], smBase + swB8(it * 32 + ks * 16 + bK, bCn + 2 * nj));
            #pragma unroll
            for (int mi = 0; mi < 2; mi++)
                #pragma unroll
                for (int ni = 0; ni < 4; ni++)
                    mma16816(acc[mi][ni], af[mi], &bf[ni >> 1][(ni & 1) * 2]);
        }

        if (it == 15) {
            // epilogue for this m-tile
            const int mt = f >> 4;
            #pragma unroll
            for (int mi = 0; mi < 2; mi++) {
                const int row = mt * 128 + wm + mi * 16 + grp;
                #pragma unroll
                for (int ni = 0; ni < 4; ni++) {
                    const int col = wn + ni * 8 + tig * 2;
                    *(float2*)(Cc + (size_t)row * 512 + col) =
                        make_float2(acc[mi][ni][0], acc[mi][ni][1]);
                    *(float2*)(Cc + (size_t)(row + 8) * 512 + col) =
                        make_float2(acc[mi][ni][2], acc[mi][ni][3]);
                    acc[mi][ni][0] = acc[mi][ni][1] = acc[mi][ni][2] = acc[mi][ni][3] = 0.f;
                }
            }
        }
    }
}

// ---------------------------------------------------------------------------
extern "C" void kernel_launch(void* const* d_in, const int* in_sizes, int n_in,
                              void* d_out, int out_size)
{
    const float* hidden = (const float*)d_in[0];
    const float* sp     = (const float*)d_in[1];
    const float* Wq     = (const float*)d_in[2];
    const float* bq     = (const float*)d_in[3];
    const float* Wk     = (const float*)d_in[4];
    const float* bk     = (const float*)d_in[5];
    const float* Wv     = (const float*)d_in[6];
    const float* bv     = (const float*)d_in[7];
    float* out = (float*)d_out;
    (void)in_sizes; (void)n_in; (void)out_size;

    __half *wqp, *wkp, *wvp, *qp, *kp, *pp, *vp;
    float* spt;
    cudaGetSymbolAddress((void**)&wqp, g_wq);
    cudaGetSymbolAddress((void**)&wkp, g_wk);
    cudaGetSymbolAddress((void**)&wvp, g_wv);
    cudaGetSymbolAddress((void**)&qp,  g_q);
    cudaGetSymbolAddress((void**)&kp,  g_k);
    cudaGetSymbolAddress((void**)&spt, g_s);
    cudaGetSymbolAddress((void**)&pp,  g_probs);
    cudaGetSymbolAddress((void**)&vp,  g_v);

    static bool attr_done = false;
    if (!attr_done) {
        cudaFuncSetAttribute(h16_ctx, cudaFuncAttributeMaxDynamicSharedMemorySize, 90112);
        cudaFuncSetAttribute(v_proj, cudaFuncAttributeMaxDynamicSharedMemorySize, 110592);
        attr_done = true;
    }

    dim3 blk(256);

    // weights fp32 -> half
    f2h3_kernel<<<dim3(256, 3), blk>>>(Wq, Wk, Wv, wqp, wkp, wvp);

    // Q/K projection + RoPE
    qk_proj<<<dim3(4, 4, 4), blk>>>(hidden, wqp, bq, qp, wkp, bk, kp, sp);

    // V projection: fp32 hidden read once, BN=512, cp.async pipeline
    v_proj<<<dim3(1024), blk, 110592>>>(hidden, wvp, bv, vp);

    // scores + softmax
    scores_kernel<<<dim3(4, 4, 16), blk>>>(qp, kp, spt);
    softmax_kernel<<<1024, blk>>>(spt, pp);

    // ctx with V-resident smem + cp.async pipeline
    h16_ctx<<<1024, blk, 90112>>>(pp, vp, out);
}

// round 8
// speedup vs baseline: 7.7399x; 1.1257x over previous
#include <cuda_runtime.h>
#include <cuda_fp16.h>
#include <cstdint>

#define LB 2
#define LR 64
#define LL 512
#define LH 1024
#define LAH 512

__device__ __half g_wq[LAH * LH], g_wk[LAH * LH], g_wv[LAH * LH];
__device__ __half g_q[(size_t)LB * LL * LAH];
__device__ __half g_k[(size_t)LB * LL * LAH];
__device__ float  g_s[(size_t)LB * 8 * LL * LL];
__device__ __half g_probs[(size_t)LB * 8 * LL * LL];
__device__ __half g_v[(size_t)LB * LR * LL * LAH];

// ---------------------------------------------------------------------------
__device__ __forceinline__ void ldsm4(uint32_t r[4], uint32_t a) {
    asm volatile("ldmatrix.sync.aligned.m8n8.x4.shared.b16 {%0,%1,%2,%3}, [%4];"
                 : "=r"(r[0]), "=r"(r[1]), "=r"(r[2]), "=r"(r[3]) : "r"(a));
}
__device__ __forceinline__ void ldsm4t(uint32_t r[4], uint32_t a) {
    asm volatile("ldmatrix.sync.aligned.m8n8.x4.trans.shared.b16 {%0,%1,%2,%3}, [%4];"
                 : "=r"(r[0]), "=r"(r[1]), "=r"(r[2]), "=r"(r[3]) : "r"(a));
}
__device__ __forceinline__ void mma16816(float c[4], const uint32_t a[4], const uint32_t b[2]) {
    asm volatile(
        "mma.sync.aligned.m16n8k16.row.col.f32.f16.f16.f32 "
        "{%0,%1,%2,%3}, {%4,%5,%6,%7}, {%8,%9}, {%0,%1,%2,%3};"
        : "+f"(c[0]), "+f"(c[1]), "+f"(c[2]), "+f"(c[3])
        : "r"(a[0]), "r"(a[1]), "r"(a[2]), "r"(a[3]), "r"(b[0]), "r"(b[1]));
}
__device__ __forceinline__ uint32_t pk2(float x, float y) {
    __half2 h = __floats2half2_rn(x, y);
    return *(uint32_t*)&h;
}
__device__ __forceinline__ uint4 cvt8(float4 a, float4 b) {
    uint4 u;
    u.x = pk2(a.x, a.y); u.y = pk2(a.z, a.w);
    u.z = pk2(b.x, b.y); u.w = pk2(b.z, b.w);
    return u;
}
// [rows][32-half] rows of 4x16B chunks, swizzle c ^ ((row>>1)&3)
__device__ __forceinline__ uint32_t swA(int row, int c) {
    return (uint32_t)((row * 4 + (c ^ ((row >> 1) & 3))) * 16);
}
// [rows][64-half] rows of 8x16B chunks (128B rows), SW128: c ^ (row&7)
__device__ __forceinline__ uint32_t swB8(int row, int c) {
    return (uint32_t)((row * 8 + (c ^ (row & 7))) * 16);
}
__device__ __forceinline__ void cpa16(uint32_t dst, const void* src) {
    asm volatile("cp.async.cg.shared.global [%0], [%1], 16;" :: "r"(dst), "l"(src));
}
__device__ __forceinline__ void cpa_commit() {
    asm volatile("cp.async.commit_group;" ::: "memory");
}
template<int N>
__device__ __forceinline__ void cpa_wait() {
    asm volatile("cp.async.wait_group %0;" :: "n"(N) : "memory");
}

// ---------------------------------------------------------------------------
// weights fp32 -> half (3 arrays in one launch): grid (256, 3)
// ---------------------------------------------------------------------------
__global__ void f2h3_kernel(const float* __restrict__ a, const float* __restrict__ b,
                            const float* __restrict__ c,
                            __half* __restrict__ da, __half* __restrict__ db,
                            __half* __restrict__ dc)
{
    const float* s; __half* d;
    if (blockIdx.y == 0)      { s = a; d = da; }
    else if (blockIdx.y == 1) { s = b; d = db; }
    else                      { s = c; d = dc; }
    const long j = ((long)blockIdx.x * 256 + threadIdx.x) * 8;
    float4 x = *(const float4*)(s + j);
    float4 y = *(const float4*)(s + j + 4);
    *(uint4*)(d + j) = cvt8(x, y);
}

// ---------------------------------------------------------------------------
// V projection: C = hidden @ Wv^T + bv (half out)
// M=65536 N=512 K=1024. BM=64, BN=512, BK=64. 8 warps, warp 32x128.
// 3-stage pipeline: B via cp.async, A via register staging (fp32->half).
// stage = A 8KB + B 64KB = 72KB; 3 stages = 216KB dynamic smem.
// ---------------------------------------------------------------------------
__global__ __launch_bounds__(256, 1)
void v_proj(const float* __restrict__ A, const __half* __restrict__ W,
            const float* __restrict__ bias, __half* __restrict__ C)
{
    extern __shared__ __align__(16) unsigned char sm[];
    const uint32_t smBase = (uint32_t)__cvta_generic_to_shared(sm);
    const int STAGE = 73728;

    const int m0 = blockIdx.x * 64;
    const int t  = threadIdx.x;
    const int lane = t & 31, wid = t >> 5;
    const int wm  = (wid & 1) * 32;
    const int wn  = (wid >> 1) * 128;
    const int grp = lane >> 2, tig = lane & 3;

    // A staging: 64 rows x 64 fp32 -> half; 4 threads/row, 2 chunks each
    const int arow = t >> 2, ac = t & 3;
    const float* Ag = A + (size_t)(m0 + arow) * 1024 + ac * 16;

    const int aRow = wm + (lane & 15);
    const int aCs  = lane >> 4;
    const int bRow = wn + (lane & 7) + 8 * (lane >> 4);
    const int bCs  = (lane >> 3) & 1;

    float acc[2][16][4] = {};

    // prologue: stages 0,1
    #pragma unroll
    for (int p = 0; p < 2; p++) {
        const int k0 = p * 64;
        const uint32_t st = smBase + p * STAGE;
        #pragma unroll
        for (int j = 0; j < 16; j++) {
            const int i = t + 256 * j;
            const int row = i >> 3, ch = i & 7;
            cpa16(st + 8192 + swB8(row, ch), W + (size_t)row * 1024 + k0 + ch * 8);
        }
        float4 x0 = *(const float4*)(Ag + k0);
        float4 y0 = *(const float4*)(Ag + k0 + 4);
        float4 x1 = *(const float4*)(Ag + k0 + 8);
        float4 y1 = *(const float4*)(Ag + k0 + 12);
        *(uint4*)(sm + p * STAGE + swB8(arow, 2 * ac))     = cvt8(x0, y0);
        *(uint4*)(sm + p * STAGE + swB8(arow, 2 * ac + 1)) = cvt8(x1, y1);
        cpa_commit();
    }

    for (int it = 0; it < 16; it++) {
        const int s = it - (it / 3) * 3;
        cpa_wait<1>();
        __syncthreads();

        // prefetch stage it+2
        float4 px0, py0, px1, py1;
        const bool pf = (it + 2 < 16);
        const int s2 = (it + 2) - ((it + 2) / 3) * 3;
        if (pf) {
            const int k0 = (it + 2) * 64;
            const uint32_t st = smBase + s2 * STAGE;
            #pragma unroll
            for (int j = 0; j < 16; j++) {
                const int i = t + 256 * j;
                const int row = i >> 3, ch = i & 7;
                cpa16(st + 8192 + swB8(row, ch), W + (size_t)row * 1024 + k0 + ch * 8);
            }
            px0 = *(const float4*)(Ag + k0);
            py0 = *(const float4*)(Ag + k0 + 4);
            px1 = *(const float4*)(Ag + k0 + 8);
            py1 = *(const float4*)(Ag + k0 + 12);
        }

        const uint32_t bA = smBase + s * STAGE;
        const uint32_t bB = bA + 8192;
        #pragma unroll
        for (int ks = 0; ks < 4; ks++) {
            uint32_t af[2][4];
            ldsm4(af[0], bA + swB8(aRow, 2 * ks + aCs));
            ldsm4(af[1], bA + swB8(aRow + 16, 2 * ks + aCs));
            #pragma unroll
            for (int nj = 0; nj < 8; nj++) {
                uint32_t bf[4];
                ldsm4(bf, bB + swB8(bRow + nj * 16, 2 * ks + bCs));
                mma16816(acc[0][2 * nj],     af[0], &bf[0]);
                mma16816(acc[0][2 * nj + 1], af[0], &bf[2]);
                mma16816(acc[1][2 * nj],     af[1], &bf[0]);
                mma16816(acc[1][2 * nj + 1], af[1], &bf[2]);
            }
        }

        if (pf) {
            unsigned char* d = sm + s2 * STAGE;
            *(uint4*)(d + swB8(arow, 2 * ac))     = cvt8(px0, py0);
            *(uint4*)(d + swB8(arow, 2 * ac + 1)) = cvt8(px1, py1);
        }
        cpa_commit();
    }

    #pragma unroll
    for (int mi = 0; mi < 2; mi++) {
        const int row = m0 + wm + mi * 16 + grp;
        #pragma unroll
        for (int ni = 0; ni < 16; ni++) {
            const int col = wn + ni * 8 + tig * 2;
            const float b0 = bias[col], b1 = bias[col + 1];
            *(__half2*)(C + (size_t)row * 512 + col) =
                __floats2half2_rn(acc[mi][ni][0] + b0, acc[mi][ni][1] + b1);
            *(__half2*)(C + (size_t)(row + 8) * 512 + col) =
                __floats2half2_rn(acc[mi][ni][2] + b0, acc[mi][ni][3] + b1);
        }
    }
}

// ---------------------------------------------------------------------------
// Q/K projection + RoPE (A fp32 in, half out)
// ---------------------------------------------------------------------------
__global__ __launch_bounds__(256)
void qk_proj(const float* __restrict__ hidden,
             const __half* __restrict__ Bq, const float* __restrict__ bq, __half* __restrict__ Cq,
             const __half* __restrict__ Bk, const float* __restrict__ bk, __half* __restrict__ Ck,
             const float* __restrict__ sp)
{
    __shared__ __align__(16) unsigned char sm[2 * 16384];
    const uint32_t smBase = (uint32_t)__cvta_generic_to_shared(sm);

    const int b = blockIdx.z >> 1, which = blockIdx.z & 1;
    const float* A = hidden + (size_t)b * ((size_t)LR * LL * LH);
    const __half* B = which ? Bk : Bq;
    const float* bias = which ? bk : bq;
    __half* C = (which ? Ck : Cq) + (size_t)b * LL * LAH;

    const int m0 = blockIdx.y * 128;
    const int n0 = blockIdx.x * 128;
    const int t  = threadIdx.x;

    const int srow = t >> 1;
    const int cb   = (t & 1) * 2;
    const float* Ag = A + (size_t)(m0 + srow) * LH + cb * 8;
    const __half* Bg = B + (size_t)(n0 + srow) * LH + cb * 8;

    const int wid  = t >> 5;
    const int wm   = (wid & 1) * 64;
    const int wn   = (wid >> 1) * 32;
    const int lane = t & 31;
    const int grp  = lane >> 2;
    const int tig  = lane & 3;

    const int aRow = wm + (lane & 15);
    const int aCs  = lane >> 4;
    const int bRow = wn + (lane & 7) + 8 * (lane >> 4);
    const int bCs  = (lane >> 3) & 1;

    float acc[4][4][4] = {};

    float4 a00, a01, a10, a11;
    uint4 b0, b1;
    a00 = *(const float4*)(Ag);      a01 = *(const float4*)(Ag + 4);
    a10 = *(const float4*)(Ag + 8);  a11 = *(const float4*)(Ag + 12);
    b0 = *(const uint4*)(Bg);        b1 = *(const uint4*)(Bg + 8);
    *(uint4*)(sm + swA(srow, cb))            = cvt8(a00, a01);
    *(uint4*)(sm + swA(srow, cb + 1))        = cvt8(a10, a11);
    *(uint4*)(sm + 8192 + swA(srow, cb))     = b0;
    *(uint4*)(sm + 8192 + swA(srow, cb + 1)) = b1;
    __syncthreads();

    const int NK = LH / 32;
    for (int it = 0; it < NK; it++) {
        const int s = it & 1;
        if (it + 1 < NK) {
            const int k0 = (it + 1) * 32;
            a00 = *(const float4*)(Ag + k0);      a01 = *(const float4*)(Ag + k0 + 4);
            a10 = *(const float4*)(Ag + k0 + 8);  a11 = *(const float4*)(Ag + k0 + 12);
            b0 = *(const uint4*)(Bg + k0);        b1 = *(const uint4*)(Bg + k0 + 8);
        }
        const uint32_t bA = smBase + s * 16384;
        const uint32_t bB = bA + 8192;
        #pragma unroll
        for (int ks = 0; ks < 2; ks++) {
            uint32_t af[4][4], bf[2][4];
            #pragma unroll
            for (int mi = 0; mi < 4; mi++)
                ldsm4(af[mi], bA + swA(aRow + mi * 16, 2 * ks + aCs));
            #pragma unroll
            for (int nj = 0; nj < 2; nj++)
                ldsm4(bf[nj], bB + swA(bRow + nj * 16, 2 * ks + bCs));
            #pragma unroll
            for (int mi = 0; mi < 4; mi++)
                #pragma unroll
                for (int ni = 0; ni < 4; ni++)
                    mma16816(acc[mi][ni], af[mi], &bf[ni >> 1][(ni & 1) * 2]);
        }
        if (it + 1 < NK) {
            unsigned char* d = sm + (s ^ 1) * 16384;
            *(uint4*)(d + swA(srow, cb))            = cvt8(a00, a01);
            *(uint4*)(d + swA(srow, cb + 1))        = cvt8(a10, a11);
            *(uint4*)(d + 8192 + swA(srow, cb))     = b0;
            *(uint4*)(d + 8192 + swA(srow, cb + 1)) = b1;
        }
        __syncthreads();
    }

    #pragma unroll
    for (int mi = 0; mi < 4; mi++) {
        const int row = m0 + wm + mi * 16 + grp;
        #pragma unroll
        for (int ni = 0; ni < 4; ni++) {
            const int col = n0 + wn + ni * 8 + tig * 2;
            const float bb0 = bias[col], bb1 = bias[col + 1];
            float c0 = acc[mi][ni][0] + bb0, c1 = acc[mi][ni][1] + bb1;
            float c2 = acc[mi][ni][2] + bb0, c3 = acc[mi][ni][3] + bb1;
            const int ii = (col & 63) >> 1;
            float sn = sp[row * 64 + ii], cs = sp[row * 64 + 32 + ii];
            float r0 = c0 * cs - c1 * sn, r1 = c1 * cs + c0 * sn;
            sn = sp[(row + 8) * 64 + ii]; cs = sp[(row + 8) * 64 + 32 + ii];
            float r2 = c2 * cs - c3 * sn, r3 = c3 * cs + c2 * sn;
            *(__half2*)(C + (size_t)row * LAH + col)       = __floats2half2_rn(r0, r1);
            *(__half2*)(C + (size_t)(row + 8) * LAH + col) = __floats2half2_rn(r2, r3);
        }
    }
}

// ---------------------------------------------------------------------------
// scores GEMM (NT): per (b,n): S = 0.125 * q @ k^T, fp32 out. K=64 single stage.
// ---------------------------------------------------------------------------
__global__ __launch_bounds__(256)
void scores_kernel(const __half* __restrict__ q, const __half* __restrict__ k,
                   float* __restrict__ s)
{
    __shared__ __align__(16) unsigned char sm[32768];
    const uint32_t smBase = (uint32_t)__cvta_generic_to_shared(sm);

    const int z = blockIdx.z;
    const int b = z >> 3, n = z & 7;
    const size_t base = (size_t)b * 512 * 512 + n * 64;

    const int m0  = blockIdx.y * 128;
    const int n0k = blockIdx.x * 128;
    const int t   = threadIdx.x;

    const int srow = t >> 1;
    const int cb   = (t & 1) * 4;
    #pragma unroll
    for (int j = 0; j < 4; j++) {
        cpa16(smBase + swB8(srow, cb + j),
              q + base + (size_t)(m0 + srow) * 512 + (cb + j) * 8);
        cpa16(smBase + 16384 + swB8(srow, cb + j),
              k + base + (size_t)(n0k + srow) * 512 + (cb + j) * 8);
    }
    cpa_commit();
    cpa_wait<0>();
    __syncthreads();

    const int wid  = t >> 5;
    const int wm   = (wid & 1) * 64;
    const int wn   = (wid >> 1) * 32;
    const int lane = t & 31;
    const int grp  = lane >> 2;
    const int tig  = lane & 3;

    const int aRow = wm + (lane & 15);
    const int aCs  = lane >> 4;
    const int bRow = wn + (lane & 7) + 8 * (lane >> 4);
    const int bCs  = (lane >> 3) & 1;

    float acc[4][4][4] = {};
    #pragma unroll
    for (int ks = 0; ks < 4; ks++) {
        uint32_t af[4][4], bf[2][4];
        #pragma unroll
        for (int mi = 0; mi < 4; mi++)
            ldsm4(af[mi], smBase + swB8(aRow + mi * 16, 2 * ks + aCs));
        #pragma unroll
        for (int nj = 0; nj < 2; nj++)
            ldsm4(bf[nj], smBase + 16384 + swB8(bRow + nj * 16, 2 * ks + bCs));
        #pragma unroll
        for (int mi = 0; mi < 4; mi++)
            #pragma unroll
            for (int ni = 0; ni < 4; ni++)
                mma16816(acc[mi][ni], af[mi], &bf[ni >> 1][(ni & 1) * 2]);
    }

    float* S = s + (size_t)z * 512 * 512;
    #pragma unroll
    for (int mi = 0; mi < 4; mi++) {
        const int row = m0 + wm + mi * 16 + grp;
        #pragma unroll
        for (int ni = 0; ni < 4; ni++) {
            const int col = n0k + wn + ni * 8 + tig * 2;
            *(float2*)(S + (size_t)row * 512 + col) =
                make_float2(acc[mi][ni][0] * 0.125f, acc[mi][ni][1] * 0.125f);
            *(float2*)(S + (size_t)(row + 8) * 512 + col) =
                make_float2(acc[mi][ni][2] * 0.125f, acc[mi][ni][3] * 0.125f);
        }
    }
}

// ---------------------------------------------------------------------------
// softmax: one warp per 512-score row -> half probs
// ---------------------------------------------------------------------------
__global__ __launch_bounds__(256)
void softmax_kernel(const float* __restrict__ s, __half* __restrict__ p)
{
    const int w    = threadIdx.x >> 5;
    const int lane = threadIdx.x & 31;
    const size_t row = (size_t)blockIdx.x * 8 + w;
    const float* src = s + row * 512;

    float4 v[4];
    float mx = -1e30f;
    #pragma unroll
    for (int j = 0; j < 4; j++) {
        v[j] = *(const float4*)(src + (lane + j * 32) * 4);
        mx = fmaxf(mx, fmaxf(fmaxf(v[j].x, v[j].y), fmaxf(v[j].z, v[j].w)));
    }
    #pragma unroll
    for (int off = 16; off; off >>= 1) mx = fmaxf(mx, __shfl_xor_sync(0xffffffffu, mx, off));

    float sum = 0.f;
    #pragma unroll
    for (int j = 0; j < 4; j++) {
        v[j].x = expf(v[j].x - mx); v[j].y = expf(v[j].y - mx);
        v[j].z = expf(v[j].z - mx); v[j].w = expf(v[j].w - mx);
        sum += v[j].x + v[j].y + v[j].z + v[j].w;
    }
    #pragma unroll
    for (int off = 16; off; off >>= 1) sum += __shfl_xor_sync(0xffffffffu, sum, off);
    const float inv = 1.f / sum;

    __half* dst = p + row * 512;
    #pragma unroll
    for (int j = 0; j < 4; j++) {
        uint2 u;
        u.x = pk2(v[j].x * inv, v[j].y * inv);
        u.y = pk2(v[j].z * inv, v[j].w * inv);
        *(uint2*)(dst + (lane + j * 32) * 4) = u;
    }
}

// ---------------------------------------------------------------------------
// ctx GEMM: per (b,n,r): V head-slice (512x64 half = 64KB) resident in smem,
// flattened 64-iter cp.async pipeline over (mt, it). BM=128 BN=64 BK=32.
// smem: V 64KB + 3 x 8KB A stages = 88KB.
// ---------------------------------------------------------------------------
__global__ __launch_bounds__(256)
void h16_ctx(const __half* __restrict__ P, const __half* __restrict__ V,
             float* __restrict__ C)
{
    extern __shared__ __align__(16) unsigned char sm[];
    const uint32_t smBase = (uint32_t)__cvta_generic_to_shared(sm);

    const int z = blockIdx.x;
    const int b = z >> 9, n = (z >> 6) & 7, r = z & 63;
    const int br = b * 64 + r;

    const __half* Vg = V + (size_t)br * (512 * 512) + n * 64;
    const __half* P0 = P + ((size_t)(b * 8 + n)) * (512 * 512);
    float*        Cc = C + (size_t)br * (512 * 512) + n * 64;

    const int t = threadIdx.x;

    // V preload via cp.async (group 0)
    #pragma unroll
    for (int j = 0; j < 16; j++) {
        const int i = t + 256 * j;
        const int row = i >> 3, ch = i & 7;
        cpa16(smBase + swB8(row, ch), Vg + (size_t)row * 512 + ch * 8);
    }
    cpa_commit();

    const int arow = t >> 1;
    const int acb  = (t & 1) * 2;

    #pragma unroll
    for (int p = 0; p < 2; p++) {
        const uint32_t st = smBase + 65536 + p * 8192;
        const __half* Am = P0 + (size_t)((p >> 4) * 128 + arow) * 512 + (p & 15) * 32 + acb * 8;
        cpa16(st + swA(arow, acb), Am);
        cpa16(st + swA(arow, acb + 1), Am + 8);
        cpa_commit();
    }

    const int wid  = t >> 5;
    const int wm   = (wid & 3) * 32;
    const int wn   = (wid >> 2) * 32;
    const int lane = t & 31;
    const int grp  = lane >> 2;
    const int tig  = lane & 3;

    const int aRow = wm + (lane & 15);
    const int aCs  = lane >> 4;
    const int bK   = (lane & 7) + 8 * ((lane >> 3) & 1);
    const int bCn  = (wn >> 3) + (lane >> 4);

    float acc[2][4][4] = {};

    for (int f = 0; f < 64; f++) {
        const int s = f - (f / 3) * 3;
        const int it = f & 15;
        cpa_wait<1>();
        __syncthreads();

        if (f + 2 < 64) {
            const int f2 = f + 2;
            const int s2 = f2 - (f2 / 3) * 3;
            const uint32_t st = smBase + 65536 + s2 * 8192;
            const __half* Am = P0 + (size_t)((f2 >> 4) * 128 + arow) * 512 + (f2 & 15) * 32 + acb * 8;
            cpa16(st + swA(arow, acb), Am);
            cpa16(st + swA(arow, acb + 1), Am + 8);
        }
        cpa_commit();

        const uint32_t bA = smBase + 65536 + s * 8192;
        #pragma unroll
        for (int ks = 0; ks < 2; ks++) {
            uint32_t af[2][4], bf[2][4];
            #pragma unroll
            for (int mi = 0; mi < 2; mi++)
                ldsm4(af[mi], bA + swA(aRow + mi * 16, 2 * ks + aCs));
            #pragma unroll
            for (int nj = 0; nj < 2; nj++)
                ldsm4t(bf[nj], smBase + swB8(it * 32 + ks * 16 + bK, bCn + 2 * nj));
            #pragma unroll
            for (int mi = 0; mi < 2; mi++)
                #pragma unroll
                for (int ni = 0; ni < 4; ni++)
                    mma16816(acc[mi][ni], af[mi], &bf[ni >> 1][(ni & 1) * 2]);
        }

        if (it == 15) {
            const int mt = f >> 4;
            #pragma unroll
            for (int mi = 0; mi < 2; mi++) {
                const int row = mt * 128 + wm + mi * 16 + grp;
                #pragma unroll
                for (int ni = 0; ni < 4; ni++) {
                    const int col = wn + ni * 8 + tig * 2;
                    *(float2*)(Cc + (size_t)row * 512 + col) =
                        make_float2(acc[mi][ni][0], acc[mi][ni][1]);
                    *(float2*)(Cc + (size_t)(row + 8) * 512 + col) =
                        make_float2(acc[mi][ni][2], acc[mi][ni][3]);
                    acc[mi][ni][0] = acc[mi][ni][1] = acc[mi][ni][2] = acc[mi][ni][3] = 0.f;
                }
            }
        }
    }
}

// ---------------------------------------------------------------------------
extern "C" void kernel_launch(void* const* d_in, const int* in_sizes, int n_in,
                              void* d_out, int out_size)
{
    const float* hidden = (const float*)d_in[0];
    const float* sp     = (const float*)d_in[1];
    const float* Wq     = (const float*)d_in[2];
    const float* bq     = (const float*)d_in[3];
    const float* Wk     = (const float*)d_in[4];
    const float* bk     = (const float*)d_in[5];
    const float* Wv     = (const float*)d_in[6];
    const float* bv     = (const float*)d_in[7];
    float* out = (float*)d_out;
    (void)in_sizes; (void)n_in; (void)out_size;

    __half *wqp, *wkp, *wvp, *qp, *kp, *pp, *vp;
    float* spt;
    cudaGetSymbolAddress((void**)&wqp, g_wq);
    cudaGetSymbolAddress((void**)&wkp, g_wk);
    cudaGetSymbolAddress((void**)&wvp, g_wv);
    cudaGetSymbolAddress((void**)&qp,  g_q);
    cudaGetSymbolAddress((void**)&kp,  g_k);
    cudaGetSymbolAddress((void**)&spt, g_s);
    cudaGetSymbolAddress((void**)&pp,  g_probs);
    cudaGetSymbolAddress((void**)&vp,  g_v);

    static cudaStream_t s2 = nullptr;
    static cudaEvent_t ev0 = nullptr, ev1 = nullptr;
    if (s2 == nullptr) {
        cudaStreamCreateWithFlags(&s2, cudaStreamNonBlocking);
        cudaEventCreateWithFlags(&ev0, cudaEventDisableTiming);
        cudaEventCreateWithFlags(&ev1, cudaEventDisableTiming);
        cudaFuncSetAttribute(h16_ctx, cudaFuncAttributeMaxDynamicSharedMemorySize, 90112);
        cudaFuncSetAttribute(v_proj, cudaFuncAttributeMaxDynamicSharedMemorySize, 221184);
    }

    dim3 blk(256);

    // weights fp32 -> half (stream 0)
    f2h3_kernel<<<dim3(256, 3), blk>>>(Wq, Wk, Wv, wqp, wkp, wvp);

    // fork: qk/scores/softmax chain on side stream, overlapped with v_proj
    cudaEventRecord(ev0, 0);
    cudaStreamWaitEvent(s2, ev0, 0);
    qk_proj<<<dim3(4, 4, 4), blk, 0, s2>>>(hidden, wqp, bq, qp, wkp, bk, kp, sp);
    scores_kernel<<<dim3(4, 4, 16), blk, 0, s2>>>(qp, kp, spt);
    softmax_kernel<<<1024, blk, 0, s2>>>(spt, pp);
    cudaEventRecord(ev1, s2);

    // V projection on stream 0 (BK=64, 3-stage cp.async)
    v_proj<<<dim3(1024), blk, 221184>>>(hidden, wvp, bv, vp);

    // join, then ctx
    cudaStreamWaitEvent(0, ev1, 0);
    h16_ctx<<<1024, blk, 90112>>>(pp, vp, out);
}